// round 12
// baseline (speedup 1.0000x reference)
#include <cuda_runtime.h>
#include <cuda_bf16.h>
#include <cuda_fp16.h>
#include <cstdint>

#define B_   2
#define S_   4096
#define DM_  1024
#define DK_  64
#define NSPLIT 4

// ===========================================================================
// Scratch (__device__ globals per allocation rules)
// ===========================================================================
__device__ __half g_q [B_ * S_ * DK_];           // q * 0.125*log2e, fp16
__device__ __half g_k [B_ * S_ * DK_];           // k single fp16
__device__ __half g_v [B_ * S_ * DK_];           // v single fp16 (row-major)
__device__ __nv_bfloat16 g_wh[3 * DK_ * DM_];    // W bf16 hi/lo (proj stays 3-pass)
__device__ __nv_bfloat16 g_wl[3 * DK_ * DM_];
__device__ uint32_t g_mb[B_ * S_ * S_ / 32];     // bitmask [b][ktile64][q] 2 words/row
__device__ float g_pacc[NSPLIT][B_ * S_ * DK_];  // per-split unnormalized O
__device__ float g_pl[NSPLIT][B_ * S_];          // per-split softmax denominators

__device__ __forceinline__ uint32_t smem_to_u32(const void* p) {
    uint32_t a;
    asm("{ .reg .u64 t; cvta.to.shared.u64 t, %1; cvt.u32.u64 %0, t; }" : "=r"(a) : "l"(p));
    return a;
}
__device__ __forceinline__ uint32_t pack_bf16(__nv_bfloat16 a, __nv_bfloat16 b) {
    return (uint32_t)__bfloat16_as_ushort(a) | ((uint32_t)__bfloat16_as_ushort(b) << 16);
}
__device__ __forceinline__ void split2(float a, float b, uint32_t& h, uint32_t& l) {
    const __nv_bfloat16 ha = __float2bfloat16(a);
    const __nv_bfloat16 hb = __float2bfloat16(b);
    h = pack_bf16(ha, hb);
    l = pack_bf16(__float2bfloat16(a - __bfloat162float(ha)),
                  __float2bfloat16(b - __bfloat162float(hb)));
}
// fast hi/lo split: hi = truncated top-16 bits (PRMT pack), lo = rn(residual)
__device__ __forceinline__ void split2_fast(float a, float b, uint32_t& h, uint32_t& l) {
    const uint32_t ia = __float_as_uint(a), ib = __float_as_uint(b);
    asm("prmt.b32 %0, %1, %2, 0x7632;" : "=r"(h) : "r"(ia), "r"(ib));
    const float ra = a - __uint_as_float(ia & 0xFFFF0000u);
    const float rb = b - __uint_as_float(ib & 0xFFFF0000u);
    asm("cvt.rn.bf16x2.f32 %0, %1, %2;" : "=r"(l) : "f"(rb), "f"(ra));
}
__device__ __forceinline__ uint32_t pack_h2(__half a, __half b) {
    const __half2 v = __halves2half2(a, b);   // a -> low
    return *(const uint32_t*)&v;
}
__device__ __forceinline__ float ex2f(float x) {
    float y;
    asm("ex2.approx.f32 %0, %1;" : "=f"(y) : "f"(x));
    return y;
}
__device__ __forceinline__ uint32_t cvt_f16x2(float lo, float hi) {
    uint32_t d;
    asm("cvt.rn.f16x2.f32 %0, %1, %2;" : "=r"(d) : "f"(hi), "f"(lo));   // lo -> low half
    return d;
}
__device__ __forceinline__ void mma_bf16(float c[4], const uint32_t a[4],
                                         uint32_t b0, uint32_t b1) {
    asm volatile("mma.sync.aligned.m16n8k16.row.col.f32.bf16.bf16.f32 "
        "{%0,%1,%2,%3}, {%4,%5,%6,%7}, {%8,%9}, {%0,%1,%2,%3};"
        : "+f"(c[0]), "+f"(c[1]), "+f"(c[2]), "+f"(c[3])
        : "r"(a[0]), "r"(a[1]), "r"(a[2]), "r"(a[3]), "r"(b0), "r"(b1));
}
__device__ __forceinline__ void mma_f16(float c[4], const uint32_t a[4],
                                        uint32_t b0, uint32_t b1) {
    asm volatile("mma.sync.aligned.m16n8k16.row.col.f32.f16.f16.f32 "
        "{%0,%1,%2,%3}, {%4,%5,%6,%7}, {%8,%9}, {%0,%1,%2,%3};"
        : "+f"(c[0]), "+f"(c[1]), "+f"(c[2]), "+f"(c[3])
        : "r"(a[0]), "r"(a[1]), "r"(a[2]), "r"(a[3]), "r"(b0), "r"(b1));
}
__device__ __forceinline__ void ldsm4(uint32_t r[4], uint32_t addr) {
    asm volatile("ldmatrix.sync.aligned.m8n8.x4.shared.b16 {%0,%1,%2,%3}, [%4];"
        : "=r"(r[0]), "=r"(r[1]), "=r"(r[2]), "=r"(r[3]) : "r"(addr));
}
__device__ __forceinline__ void ldsm4t(uint32_t r[4], uint32_t addr) {
    asm volatile("ldmatrix.sync.aligned.m8n8.x4.trans.shared.b16 {%0,%1,%2,%3}, [%4];"
        : "=r"(r[0]), "=r"(r[1]), "=r"(r[2]), "=r"(r[3]) : "r"(addr));
}
__device__ __forceinline__ void cp16(uint32_t smem, const void* g) {
    asm volatile("cp.async.cg.shared.global [%0], [%1], 16;" :: "r"(smem), "l"(g));
}
__device__ __forceinline__ void cp_commit() {
    asm volatile("cp.async.commit_group;");
}
template <int N>
__device__ __forceinline__ void cp_wait() {
    asm volatile("cp.async.wait_group %0;" :: "n"(N));
}

// ===========================================================================
// prep_w: convert Wq/Wk/Wv fp32 -> bf16 hi/lo once.  grid (64, 3) x 256
// ===========================================================================
__global__ __launch_bounds__(256)
void prep_w(const float* __restrict__ Wq, const float* __restrict__ Wk,
            const float* __restrict__ Wv)
{
    const int which = blockIdx.y;
    const float* W = (which == 0) ? Wq : (which == 1) ? Wk : Wv;
    const int n = blockIdx.x;
    const int col = threadIdx.x * 4;
    const float4 v = *(const float4*)(W + n * DM_ + col);
    uint32_t h0, l0, h1, l1;
    split2(v.x, v.y, h0, l0);
    split2(v.z, v.w, h1, l1);
    const size_t off = (size_t)which * DK_ * DM_ + n * DM_ + col;
    *(uint2*)(g_wh + off) = make_uint2(h0, h1);
    *(uint2*)(g_wl + off) = make_uint2(l0, l1);
}

// ===========================================================================
// proj_tc: grid (128, 4) x 128.
//  which 0..2 : C[8192x64] = A @ W^T + bias, bf16 hi/lo 3-pass mma, pipelined.
//               single-fp16 emit; q pre-scaled by 0.125*log2(e).
//  which == 3 : mask int32 -> bitmask g_mb.  Throughput-oriented: each warp
//               256 iterations x 8 independent LDGs, register double-buffer.
// ===========================================================================
#define PSM_AH 0
#define PSM_AL 8192
#define PSM_W  16384          /* + stage*16384 ; WH +0, WL +8192 */
#define PSM_TOTAL 49152
#define QSCALE 0.1803368801f  /* 0.125 * log2(e) */

__global__ __launch_bounds__(128)
void proj_tc(const float* __restrict__ Qin, const float* __restrict__ Kin,
             const float* __restrict__ Vin,
             const float* __restrict__ bq, const float* __restrict__ bk,
             const float* __restrict__ bv,
             const int* __restrict__ mask)
{
    const int which = blockIdx.y;
    const int tid  = threadIdx.x;
    const int wid  = tid >> 5;
    const int lane = tid & 31;

    if (which == 3) {
        // Warp W handles pair-rows [W*1024, W*1024+1024) of P = (b*64+kt)*4096+q
        // (1024 q-rows within a single (b, kt)).  Per iteration: 4 q-rows x 2
        // ballot words = 8 independent 128B loads; double-buffered in regs.
        const int W = blockIdx.x * 4 + wid;          // 0..511
        const int p0 = W * 1024;
        const int b  = p0 >> 18;
        const int kt = (p0 >> 12) & 63;
        const int q0 = p0 & 4095;                    // multiple of 1024
        const int* src = mask + ((size_t)(b * S_ + q0)) * S_ + kt * 64 + lane;
        uint32_t* dst = g_mb + ((size_t)(b * 64 + kt) * S_ + q0) * 2;

        int v[2][8];
#pragma unroll
        for (int j = 0; j < 4; j++) {
            v[0][2 * j]     = src[(size_t)j * S_];
            v[0][2 * j + 1] = src[(size_t)j * S_ + 32];
        }
        for (int i = 0; i < 256; i++) {
            const int cur = i & 1;
            if (i + 1 < 256) {
                const int* s2 = src + (size_t)((i + 1) * 4) * S_;
#pragma unroll
                for (int j = 0; j < 4; j++) {
                    v[cur ^ 1][2 * j]     = s2[(size_t)j * S_];
                    v[cur ^ 1][2 * j + 1] = s2[(size_t)j * S_ + 32];
                }
            }
            uint32_t bits[8];
#pragma unroll
            for (int j = 0; j < 8; j++)
                bits[j] = __ballot_sync(0xffffffffu, v[cur][j] != 0);
            if (lane == 0) {
                *(uint4*)(dst + i * 8)     = make_uint4(bits[0], bits[1], bits[2], bits[3]);
                *(uint4*)(dst + i * 8 + 4) = make_uint4(bits[4], bits[5], bits[6], bits[7]);
            }
        }
        return;
    }

    extern __shared__ char ps[];
    const uint32_t sb = smem_to_u32(ps);

    const float* A    = (which == 0) ? Qin : (which == 1) ? Kin : Vin;
    const float* bias = (which == 0) ? bq  : (which == 1) ? bk  : bv;
    __half* D         = (which == 0) ? g_q : (which == 1) ? g_k : g_v;
    const float osc   = (which == 0) ? QSCALE : 1.0f;
    const __nv_bfloat16* Wh = g_wh + (size_t)which * DK_ * DM_;
    const __nv_bfloat16* Wl = g_wl + (size_t)which * DK_ * DM_;

    const int m0 = blockIdx.x * 64;

    float c[8][4];
#pragma unroll
    for (int i = 0; i < 8; i++)
#pragma unroll
        for (int j = 0; j < 4; j++) c[i][j] = 0.f;

    const int arow  = wid * 16 + ((lane >> 3) & 1) * 8 + (lane & 7);
    const int acsel = lane >> 4;
    const int brow  = ((lane >> 4) << 3) + (lane & 7);
    const int bcsel = (lane >> 3) & 1;

    const int pr[4] = { (tid + 0)   >> 3, (tid + 128) >> 3,
                        (tid + 256) >> 3, (tid + 384) >> 3 };
    const int pg    = tid & 7;

    auto fillW = [&](int kc, int st) {
        const uint32_t wb = sb + PSM_W + st * 16384;
#pragma unroll
        for (int idx = tid; idx < 512; idx += 128) {
            const int n = idx >> 3, g = idx & 7;
            const uint32_t off = (uint32_t)(n * 128 + ((g ^ (n & 7)) * 16));
            cp16(wb + off,        Wh + (size_t)n * DM_ + kc * 64 + g * 8);
            cp16(wb + 8192 + off, Wl + (size_t)n * DM_ + kc * 64 + g * 8);
        }
        cp_commit();
    };

    float4 aPre[8];
#pragma unroll
    for (int i = 0; i < 4; i++) {
        const float* src = A + (size_t)(m0 + pr[i]) * DM_ + pg * 8;
        aPre[2 * i]     = *(const float4*)src;
        aPre[2 * i + 1] = *(const float4*)(src + 4);
    }
    fillW(0, 0);

    for (int kc = 0; kc < 16; kc++) {
        cp_wait<0>();
        __syncthreads();
#pragma unroll
        for (int i = 0; i < 4; i++) {
            uint4 hv, lv;
            split2_fast(aPre[2 * i].x,     aPre[2 * i].y,     hv.x, lv.x);
            split2_fast(aPre[2 * i].z,     aPre[2 * i].w,     hv.y, lv.y);
            split2_fast(aPre[2 * i + 1].x, aPre[2 * i + 1].y, hv.z, lv.z);
            split2_fast(aPre[2 * i + 1].z, aPre[2 * i + 1].w, hv.w, lv.w);
            const uint32_t off = (uint32_t)(pr[i] * 128 + ((pg ^ (pr[i] & 7)) * 16));
            *(uint4*)(ps + PSM_AH + off) = hv;
            *(uint4*)(ps + PSM_AL + off) = lv;
        }
        if (kc < 15) {
#pragma unroll
            for (int i = 0; i < 4; i++) {
                const float* src = A + (size_t)(m0 + pr[i]) * DM_ + (kc + 1) * 64 + pg * 8;
                aPre[2 * i]     = *(const float4*)src;
                aPre[2 * i + 1] = *(const float4*)(src + 4);
            }
            fillW(kc + 1, (kc + 1) & 1);
        }
        __syncthreads();

        const uint32_t a_Ah = sb + PSM_AH;
        const uint32_t a_Al = sb + PSM_AL;
        const uint32_t a_Wh = sb + PSM_W + (kc & 1) * 16384;
        const uint32_t a_Wl = a_Wh + 8192;

        uint32_t ah[4][4], al[4][4];
#pragma unroll
        for (int k4 = 0; k4 < 4; k4++) {
            const int ch = k4 * 2 + acsel;
            const uint32_t off = (uint32_t)(arow * 128 + ((ch ^ (arow & 7)) * 16));
            ldsm4(ah[k4], a_Ah + off);
            ldsm4(al[k4], a_Al + off);
        }
#pragma unroll
        for (int nt = 0; nt < 4; nt++) {
            const int row = nt * 16 + brow;
#pragma unroll
            for (int k4 = 0; k4 < 4; k4++) {
                const int ch = k4 * 2 + bcsel;
                const uint32_t off = (uint32_t)(row * 128 + ((ch ^ (row & 7)) * 16));
                uint32_t wh[4], wl[4];
                ldsm4(wh, a_Wh + off);
                ldsm4(wl, a_Wl + off);
                mma_bf16(c[nt * 2],     ah[k4], wh[0], wh[1]);
                mma_bf16(c[nt * 2],     ah[k4], wl[0], wl[1]);
                mma_bf16(c[nt * 2],     al[k4], wh[0], wh[1]);
                mma_bf16(c[nt * 2 + 1], ah[k4], wh[2], wh[3]);
                mma_bf16(c[nt * 2 + 1], ah[k4], wl[2], wl[3]);
                mma_bf16(c[nt * 2 + 1], al[k4], wh[2], wh[3]);
            }
        }
    }

    // epilogue: bias (+ q pre-scale) + single fp16 emit
    const int grp = lane >> 2;
    const int qp  = (lane & 3) * 2;
    const size_t row0 = (size_t)(m0 + wid * 16 + grp);
    const size_t row1 = row0 + 8;
#pragma unroll
    for (int nt = 0; nt < 8; nt++) {
        const int col = nt * 8 + qp;
        const float b0 = bias[col], b1 = bias[col + 1];
        *(uint32_t*)(D + row0 * DK_ + col) =
            pack_h2(__float2half_rn((c[nt][0] + b0) * osc),
                    __float2half_rn((c[nt][1] + b1) * osc));
        *(uint32_t*)(D + row1 * DK_ + col) =
            pack_h2(__float2half_rn((c[nt][2] + b0) * osc),
                    __float2half_rn((c[nt][3] + b1) * osc));
    }
}

// ===========================================================================
// attention: 64-q CTA (4 warps x 16 rows), 64-key tiles, kv-split 4.
// Single-pass fp16; ex2 softmax; l via ones-mma; bitmask from g_mb.
// per-stage smem: K 8K | V 8K | mask 512B = 16896;  x2 stages = 33792
// ===========================================================================
#define AST       16896
#define ASM_TOTAL 33792
#define ONES_H2   0x3C003C00u

__global__ __launch_bounds__(128)
void attn_mma_kernel()
{
    extern __shared__ char sm[];
    const uint32_t sb = smem_to_u32(sm);

    const int tid  = threadIdx.x;
    const int wid  = tid >> 5;
    const int lane = tid & 31;
    const int grp  = lane >> 2;
    const int qp   = (lane & 3) * 2;

    const int b     = blockIdx.y;
    const int sp    = blockIdx.z;
    const int q0    = blockIdx.x * 64;
    const int kbase = sp * (S_ / NSPLIT);
    const int qrow0 = q0 + wid * 16;
    const size_t bS = (size_t)b * S_;

    // Q fragments (single fp16, pre-scaled) from global, A-frag m16k16 layout
    uint32_t qh[4][4];
    {
        const size_t r0 = (bS + qrow0 + grp) * DK_;
        const size_t r1 = r0 + 8 * DK_;
#pragma unroll
        for (int c = 0; c < 4; c++) {
            qh[c][0] = *(const uint32_t*)(g_q + r0 + c * 16 + qp);
            qh[c][1] = *(const uint32_t*)(g_q + r1 + c * 16 + qp);
            qh[c][2] = *(const uint32_t*)(g_q + r0 + c * 16 + qp + 8);
            qh[c][3] = *(const uint32_t*)(g_q + r1 + c * 16 + qp + 8);
        }
    }

    float O[32];
#pragma unroll
    for (int i = 0; i < 32; i++) O[i] = 0.f;
    float lacc[4] = {0.f, 0.f, 0.f, 0.f};   // ones-mma accumulator (row sums)

    const int k_rhalf = (lane >> 4) << 3;
    const int k_csel  = (lane >> 3) & 1;
    const int k_i     = lane & 7;
    const int v_rhalf = ((lane >> 3) & 1) << 3;
    const int v_csel  = lane >> 4;

    auto fill = [&](int tt) {
        const int st = tt & 1;
        const uint32_t base = sb + st * AST;
        const int kk0 = kbase + tt * 64;
        const size_t krow = bS + kk0;
#pragma unroll
        for (int idx = tid; idx < 512; idx += 128) {
            const int r = idx >> 3, g = idx & 7;
            const uint32_t off = (uint32_t)(r * 128 + ((g ^ (r & 7)) * 16));
            const size_t so = (krow + r) * DK_ + g * 8;
            cp16(base + off,        g_k + so);
            cp16(base + 8192 + off, g_v + so);
        }
        // mask bits: 64 rows x 8 B, contiguous in g_mb tile-major layout
        if (tid < 32) {
            const size_t mo = ((size_t)(b * 64 + (kk0 >> 6)) * S_ + q0) * 2 + tid * 4;
            cp16(base + 16384 + tid * 16, g_mb + mo);
        }
        cp_commit();
    };

    fill(0);

    const int NT = S_ / NSPLIT / 64;   // 16 tiles
    for (int t = 0; t < NT; t++) {
        cp_wait<0>();
        __syncthreads();
        if (t + 1 < NT) fill(t + 1);

        const int st = t & 1;
        const uint32_t a_k = sb + st * AST;
        const uint32_t a_v = a_k + 8192;

        // per-tile mask bits for this thread's two q rows
        const uint2 mr0 = *(const uint2*)(sm + st * AST + 16384 + (wid * 16 + grp) * 8);
        const uint2 mr1 = *(const uint2*)(sm + st * AST + 16384 + (wid * 16 + grp + 8) * 8);

        // ---- scores + softmax + P fragments  (scores arrive pre-scaled: p = 2^cc)
        uint32_t ph[4][4];
#pragma unroll
        for (int nt2 = 0; nt2 < 4; nt2++) {
            float cA[4] = {0.f, 0.f, 0.f, 0.f};
            float cB[4] = {0.f, 0.f, 0.f, 0.f};
#pragma unroll
            for (int c = 0; c < 4; c++) {
                const int row = nt2 * 16 + k_rhalf + k_i;
                const uint32_t off = (uint32_t)(row * 128 + (((c * 2 + k_csel) ^ (row & 7)) * 16));
                uint32_t bh[4];
                ldsm4(bh, a_k + off);
                mma_f16(cA, qh[c], bh[0], bh[1]);
                mma_f16(cB, qh[c], bh[2], bh[3]);
            }
#pragma unroll
            for (int half = 0; half < 2; half++) {
                float* cc = half ? cB : cA;
                const int base = nt2 * 16 + half * 8;               // compile-time
                const uint32_t w0 = (base & 32) ? mr0.y : mr0.x;
                const uint32_t w1 = (base & 32) ? mr1.y : mr1.x;
                const int sh = (base & 31) + qp;
                const uint32_t b0 = w0 >> sh;
                const uint32_t b1 = w1 >> sh;
                const float p0 = ex2f((b0 & 1u) ? cc[0] : -127.f);
                const float p1 = ex2f((b0 & 2u) ? cc[1] : -127.f);
                const float p2 = ex2f((b1 & 1u) ? cc[2] : -127.f);
                const float p3 = ex2f((b1 & 2u) ? cc[3] : -127.f);
                ph[nt2][half * 2 + 0] = cvt_f16x2(p0, p1);
                ph[nt2][half * 2 + 1] = cvt_f16x2(p2, p3);
            }
            // l += P @ ones  (row sums, fp32 accumulate; all 8 cols identical)
            mma_f16(lacc, ph[nt2], ONES_H2, ONES_H2);
        }

        // ---- O += P @ V  (single pass; row-major V via ldmatrix.trans)
#pragma unroll
        for (int dt2 = 0; dt2 < 4; dt2++) {
            float* oA = &O[dt2 * 8];
            float* oB = &O[dt2 * 8 + 4];
#pragma unroll
            for (int kc = 0; kc < 4; kc++) {
                const int row = kc * 16 + v_rhalf + k_i;
                const uint32_t off = (uint32_t)(row * 128 + (((dt2 * 2 + v_csel) ^ (row & 7)) * 16));
                uint32_t bh[4];
                ldsm4t(bh, a_v + off);
                mma_f16(oA, ph[kc], bh[0], bh[1]);
                mma_f16(oB, ph[kc], bh[2], bh[3]);
            }
        }
        __syncthreads();   // all warps done with stage st before it is refilled
    }

    // ---- epilogue (lacc cols identical within quad; lacc[0]=row, lacc[2]=row+8)
    if ((lane & 3) == 0) {
        g_pl[sp][bS + qrow0 + grp]     = lacc[0];
        g_pl[sp][bS + qrow0 + grp + 8] = lacc[2];
    }
    float* dst0 = g_pacc[sp] + (bS + qrow0 + grp) * DK_;
    float* dst1 = dst0 + 8 * DK_;
#pragma unroll
    for (int dt = 0; dt < 8; dt++) {
        const int col = dt * 8 + qp;
        *(float2*)(dst0 + col) = make_float2(O[dt * 4 + 0], O[dt * 4 + 1]);
        *(float2*)(dst1 + col) = make_float2(O[dt * 4 + 2], O[dt * 4 + 3]);
    }
}

// ===========================================================================
// Merge the kv-splits: y = sum(acc) / sum(l)
// ===========================================================================
__global__ __launch_bounds__(256)
void merge_kernel(float* __restrict__ out)
{
    const int idx = blockIdx.x * 256 + threadIdx.x;
    const int r = idx >> 6;
    float l = 0.f, a = 0.f;
#pragma unroll
    for (int s = 0; s < NSPLIT; s++) {
        l += g_pl[s][r];
        a += g_pacc[s][idx];
    }
    out[idx] = a / l;
}

// ===========================================================================
extern "C" void kernel_launch(void* const* d_in, const int* in_sizes, int n_in,
                              void* d_out, int out_size)
{
    const float* Q    = (const float*)d_in[0];
    const float* K    = (const float*)d_in[1];
    const float* V    = (const float*)d_in[2];
    const int*   mask = (const int*)  d_in[3];
    const float* Wq   = (const float*)d_in[4];
    const float* bq   = (const float*)d_in[5];
    const float* Wk   = (const float*)d_in[6];
    const float* bk   = (const float*)d_in[7];
    const float* Wv   = (const float*)d_in[8];
    const float* bv   = (const float*)d_in[9];
    float* out = (float*)d_out;

    prep_w<<<dim3(DK_, 3), 256>>>(Wq, Wk, Wv);

    cudaFuncSetAttribute(proj_tc, cudaFuncAttributeMaxDynamicSharedMemorySize, PSM_TOTAL);
    proj_tc<<<dim3((B_ * S_) / 64, 4), 128, PSM_TOTAL>>>(Q, K, V, bq, bk, bv, mask);

    cudaFuncSetAttribute(attn_mma_kernel,
                         cudaFuncAttributeMaxDynamicSharedMemorySize, ASM_TOTAL);
    attn_mma_kernel<<<dim3(S_ / 64, B_, NSPLIT), 128, ASM_TOTAL>>>();

    merge_kernel<<<(B_ * S_ * DK_) / 256, 256>>>(out);
}

// round 13
// speedup vs baseline: 4.5017x; 4.5017x over previous
#include <cuda_runtime.h>
#include <cuda_bf16.h>
#include <cuda_fp16.h>
#include <cstdint>

#define B_   2
#define S_   4096
#define DM_  1024
#define DK_  64
#define NSPLIT 4

// ===========================================================================
// Scratch (__device__ globals per allocation rules)
// ===========================================================================
__device__ __half g_q [B_ * S_ * DK_];           // q * 0.125*log2e, fp16
__device__ __half g_k [B_ * S_ * DK_];           // k single fp16
__device__ __half g_v [B_ * S_ * DK_];           // v single fp16 (row-major)
__device__ __nv_bfloat16 g_wh[3 * DK_ * DM_];    // W bf16 hi/lo (proj stays 3-pass)
__device__ __nv_bfloat16 g_wl[3 * DK_ * DM_];
__device__ float g_pacc[NSPLIT][B_ * S_ * DK_];  // per-split unnormalized O
__device__ float g_pl[NSPLIT][B_ * S_];          // per-split softmax denominators

__device__ __forceinline__ uint32_t smem_to_u32(const void* p) {
    uint32_t a;
    asm("{ .reg .u64 t; cvta.to.shared.u64 t, %1; cvt.u32.u64 %0, t; }" : "=r"(a) : "l"(p));
    return a;
}
__device__ __forceinline__ uint32_t pack_bf16(__nv_bfloat16 a, __nv_bfloat16 b) {
    return (uint32_t)__bfloat16_as_ushort(a) | ((uint32_t)__bfloat16_as_ushort(b) << 16);
}
__device__ __forceinline__ void split2(float a, float b, uint32_t& h, uint32_t& l) {
    const __nv_bfloat16 ha = __float2bfloat16(a);
    const __nv_bfloat16 hb = __float2bfloat16(b);
    h = pack_bf16(ha, hb);
    l = pack_bf16(__float2bfloat16(a - __bfloat162float(ha)),
                  __float2bfloat16(b - __bfloat162float(hb)));
}
// fast hi/lo split: hi = truncated top-16 bits (PRMT pack), lo = rn(residual)
__device__ __forceinline__ void split2_fast(float a, float b, uint32_t& h, uint32_t& l) {
    const uint32_t ia = __float_as_uint(a), ib = __float_as_uint(b);
    asm("prmt.b32 %0, %1, %2, 0x7632;" : "=r"(h) : "r"(ia), "r"(ib));
    const float ra = a - __uint_as_float(ia & 0xFFFF0000u);
    const float rb = b - __uint_as_float(ib & 0xFFFF0000u);
    asm("cvt.rn.bf16x2.f32 %0, %1, %2;" : "=r"(l) : "f"(rb), "f"(ra));
}
__device__ __forceinline__ uint32_t pack_h2(__half a, __half b) {
    const __half2 v = __halves2half2(a, b);   // a -> low
    return *(const uint32_t*)&v;
}
__device__ __forceinline__ float ex2f(float x) {
    float y;
    asm("ex2.approx.f32 %0, %1;" : "=f"(y) : "f"(x));
    return y;
}
__device__ __forceinline__ uint32_t cvt_f16x2(float lo, float hi) {
    uint32_t d;
    asm("cvt.rn.f16x2.f32 %0, %1, %2;" : "=r"(d) : "f"(hi), "f"(lo));   // lo -> low half
    return d;
}
__device__ __forceinline__ void mma_bf16(float c[4], const uint32_t a[4],
                                         uint32_t b0, uint32_t b1) {
    asm volatile("mma.sync.aligned.m16n8k16.row.col.f32.bf16.bf16.f32 "
        "{%0,%1,%2,%3}, {%4,%5,%6,%7}, {%8,%9}, {%0,%1,%2,%3};"
        : "+f"(c[0]), "+f"(c[1]), "+f"(c[2]), "+f"(c[3])
        : "r"(a[0]), "r"(a[1]), "r"(a[2]), "r"(a[3]), "r"(b0), "r"(b1));
}
__device__ __forceinline__ void mma_f16(float c[4], const uint32_t a[4],
                                        uint32_t b0, uint32_t b1) {
    asm volatile("mma.sync.aligned.m16n8k16.row.col.f32.f16.f16.f32 "
        "{%0,%1,%2,%3}, {%4,%5,%6,%7}, {%8,%9}, {%0,%1,%2,%3};"
        : "+f"(c[0]), "+f"(c[1]), "+f"(c[2]), "+f"(c[3])
        : "r"(a[0]), "r"(a[1]), "r"(a[2]), "r"(a[3]), "r"(b0), "r"(b1));
}
__device__ __forceinline__ void ldsm4(uint32_t r[4], uint32_t addr) {
    asm volatile("ldmatrix.sync.aligned.m8n8.x4.shared.b16 {%0,%1,%2,%3}, [%4];"
        : "=r"(r[0]), "=r"(r[1]), "=r"(r[2]), "=r"(r[3]) : "r"(addr));
}
__device__ __forceinline__ void ldsm4t(uint32_t r[4], uint32_t addr) {
    asm volatile("ldmatrix.sync.aligned.m8n8.x4.trans.shared.b16 {%0,%1,%2,%3}, [%4];"
        : "=r"(r[0]), "=r"(r[1]), "=r"(r[2]), "=r"(r[3]) : "r"(addr));
}
__device__ __forceinline__ void cp16(uint32_t smem, const void* g) {
    asm volatile("cp.async.cg.shared.global [%0], [%1], 16;" :: "r"(smem), "l"(g));
}
__device__ __forceinline__ void cp_commit() {
    asm volatile("cp.async.commit_group;");
}
template <int N>
__device__ __forceinline__ void cp_wait() {
    asm volatile("cp.async.wait_group %0;" :: "n"(N));
}

// ===========================================================================
// prep_w: convert Wq/Wk/Wv fp32 -> bf16 hi/lo once.  grid (64, 3) x 256
// ===========================================================================
__global__ __launch_bounds__(256)
void prep_w(const float* __restrict__ Wq, const float* __restrict__ Wk,
            const float* __restrict__ Wv)
{
    const int which = blockIdx.y;
    const float* W = (which == 0) ? Wq : (which == 1) ? Wk : Wv;
    const int n = blockIdx.x;
    const int col = threadIdx.x * 4;
    const float4 v = *(const float4*)(W + n * DM_ + col);
    uint32_t h0, l0, h1, l1;
    split2(v.x, v.y, h0, l0);
    split2(v.z, v.w, h1, l1);
    const size_t off = (size_t)which * DK_ * DM_ + n * DM_ + col;
    *(uint2*)(g_wh + off) = make_uint2(h0, h1);
    *(uint2*)(g_wl + off) = make_uint2(l0, l1);
}

// ===========================================================================
// proj_tc: C[8192x64] = A @ W^T + bias, bf16 hi/lo 3-pass mma, pipelined.
// Epilogue: single-fp16 emit; q pre-scaled by 0.125*log2(e).
// CTA: 64 rows (4 warps x 16), K-chunks of 64.  grid (128, 3) x 128.
// ===========================================================================
#define PSM_AH 0
#define PSM_AL 8192
#define PSM_W  16384          /* + stage*16384 ; WH +0, WL +8192 */
#define PSM_TOTAL 49152
#define QSCALE 0.1803368801f  /* 0.125 * log2(e) */

__global__ __launch_bounds__(128)
void proj_tc(const float* __restrict__ Qin, const float* __restrict__ Kin,
             const float* __restrict__ Vin,
             const float* __restrict__ bq, const float* __restrict__ bk,
             const float* __restrict__ bv)
{
    extern __shared__ char ps[];
    const uint32_t sb = smem_to_u32(ps);

    const int which = blockIdx.y;
    const int tid  = threadIdx.x;
    const int wid  = tid >> 5;
    const int lane = tid & 31;

    const float* A    = (which == 0) ? Qin : (which == 1) ? Kin : Vin;
    const float* bias = (which == 0) ? bq  : (which == 1) ? bk  : bv;
    __half* D         = (which == 0) ? g_q : (which == 1) ? g_k : g_v;
    const float osc   = (which == 0) ? QSCALE : 1.0f;
    const __nv_bfloat16* Wh = g_wh + (size_t)which * DK_ * DM_;
    const __nv_bfloat16* Wl = g_wl + (size_t)which * DK_ * DM_;

    const int m0 = blockIdx.x * 64;

    float c[8][4];
#pragma unroll
    for (int i = 0; i < 8; i++)
#pragma unroll
        for (int j = 0; j < 4; j++) c[i][j] = 0.f;

    const int arow  = wid * 16 + ((lane >> 3) & 1) * 8 + (lane & 7);
    const int acsel = lane >> 4;
    const int brow  = ((lane >> 4) << 3) + (lane & 7);
    const int bcsel = (lane >> 3) & 1;

    const int pr[4] = { (tid + 0)   >> 3, (tid + 128) >> 3,
                        (tid + 256) >> 3, (tid + 384) >> 3 };
    const int pg    = tid & 7;

    auto fillW = [&](int kc, int st) {
        const uint32_t wb = sb + PSM_W + st * 16384;
#pragma unroll
        for (int idx = tid; idx < 512; idx += 128) {
            const int n = idx >> 3, g = idx & 7;
            const uint32_t off = (uint32_t)(n * 128 + ((g ^ (n & 7)) * 16));
            cp16(wb + off,        Wh + (size_t)n * DM_ + kc * 64 + g * 8);
            cp16(wb + 8192 + off, Wl + (size_t)n * DM_ + kc * 64 + g * 8);
        }
        cp_commit();
    };

    float4 aPre[8];
#pragma unroll
    for (int i = 0; i < 4; i++) {
        const float* src = A + (size_t)(m0 + pr[i]) * DM_ + pg * 8;
        aPre[2 * i]     = *(const float4*)src;
        aPre[2 * i + 1] = *(const float4*)(src + 4);
    }
    fillW(0, 0);

    for (int kc = 0; kc < 16; kc++) {
        cp_wait<0>();
        __syncthreads();
#pragma unroll
        for (int i = 0; i < 4; i++) {
            uint4 hv, lv;
            split2_fast(aPre[2 * i].x,     aPre[2 * i].y,     hv.x, lv.x);
            split2_fast(aPre[2 * i].z,     aPre[2 * i].w,     hv.y, lv.y);
            split2_fast(aPre[2 * i + 1].x, aPre[2 * i + 1].y, hv.z, lv.z);
            split2_fast(aPre[2 * i + 1].z, aPre[2 * i + 1].w, hv.w, lv.w);
            const uint32_t off = (uint32_t)(pr[i] * 128 + ((pg ^ (pr[i] & 7)) * 16));
            *(uint4*)(ps + PSM_AH + off) = hv;
            *(uint4*)(ps + PSM_AL + off) = lv;
        }
        if (kc < 15) {
#pragma unroll
            for (int i = 0; i < 4; i++) {
                const float* src = A + (size_t)(m0 + pr[i]) * DM_ + (kc + 1) * 64 + pg * 8;
                aPre[2 * i]     = *(const float4*)src;
                aPre[2 * i + 1] = *(const float4*)(src + 4);
            }
            fillW(kc + 1, (kc + 1) & 1);
        }
        __syncthreads();

        const uint32_t a_Ah = sb + PSM_AH;
        const uint32_t a_Al = sb + PSM_AL;
        const uint32_t a_Wh = sb + PSM_W + (kc & 1) * 16384;
        const uint32_t a_Wl = a_Wh + 8192;

        uint32_t ah[4][4], al[4][4];
#pragma unroll
        for (int k4 = 0; k4 < 4; k4++) {
            const int ch = k4 * 2 + acsel;
            const uint32_t off = (uint32_t)(arow * 128 + ((ch ^ (arow & 7)) * 16));
            ldsm4(ah[k4], a_Ah + off);
            ldsm4(al[k4], a_Al + off);
        }
#pragma unroll
        for (int nt = 0; nt < 4; nt++) {
            const int row = nt * 16 + brow;
#pragma unroll
            for (int k4 = 0; k4 < 4; k4++) {
                const int ch = k4 * 2 + bcsel;
                const uint32_t off = (uint32_t)(row * 128 + ((ch ^ (row & 7)) * 16));
                uint32_t wh[4], wl[4];
                ldsm4(wh, a_Wh + off);
                ldsm4(wl, a_Wl + off);
                mma_bf16(c[nt * 2],     ah[k4], wh[0], wh[1]);
                mma_bf16(c[nt * 2],     ah[k4], wl[0], wl[1]);
                mma_bf16(c[nt * 2],     al[k4], wh[0], wh[1]);
                mma_bf16(c[nt * 2 + 1], ah[k4], wh[2], wh[3]);
                mma_bf16(c[nt * 2 + 1], ah[k4], wl[2], wl[3]);
                mma_bf16(c[nt * 2 + 1], al[k4], wh[2], wh[3]);
            }
        }
    }

    // epilogue: bias (+ q pre-scale) + single fp16 emit
    const int grp = lane >> 2;
    const int qp  = (lane & 3) * 2;
    const size_t row0 = (size_t)(m0 + wid * 16 + grp);
    const size_t row1 = row0 + 8;
#pragma unroll
    for (int nt = 0; nt < 8; nt++) {
        const int col = nt * 8 + qp;
        const float b0 = bias[col], b1 = bias[col + 1];
        *(uint32_t*)(D + row0 * DK_ + col) =
            pack_h2(__float2half_rn((c[nt][0] + b0) * osc),
                    __float2half_rn((c[nt][1] + b1) * osc));
        *(uint32_t*)(D + row1 * DK_ + col) =
            pack_h2(__float2half_rn((c[nt][2] + b0) * osc),
                    __float2half_rn((c[nt][3] + b1) * osc));
    }
}

// ===========================================================================
// attention: 64-q CTA (4 warps x 16 rows), 64-key tiles, kv-split 4.
// Single-pass fp16; ex2 softmax; l via ones-mma.
// Mask read DIRECTLY from global (int2, register-prefetched one phase ahead).
// per-stage smem: K 8K | V 8K = 16384;  x2 stages = 32768 -> single wave.
// ===========================================================================
#define AST       16384
#define ASM_TOTAL 32768
#define ONES_H2   0x3C003C00u

__global__ __launch_bounds__(128)
void attn_mma_kernel(const int* __restrict__ mask)
{
    extern __shared__ char sm[];
    const uint32_t sb = smem_to_u32(sm);

    const int tid  = threadIdx.x;
    const int wid  = tid >> 5;
    const int lane = tid & 31;
    const int grp  = lane >> 2;
    const int qp   = (lane & 3) * 2;

    const int b     = blockIdx.y;
    const int sp    = blockIdx.z;
    const int q0    = blockIdx.x * 64;
    const int kbase = sp * (S_ / NSPLIT);
    const int qrow0 = q0 + wid * 16;
    const size_t bS = (size_t)b * S_;

    // Q fragments (single fp16, pre-scaled) from global, A-frag m16k16 layout
    uint32_t qh[4][4];
    {
        const size_t r0 = (bS + qrow0 + grp) * DK_;
        const size_t r1 = r0 + 8 * DK_;
#pragma unroll
        for (int c = 0; c < 4; c++) {
            qh[c][0] = *(const uint32_t*)(g_q + r0 + c * 16 + qp);
            qh[c][1] = *(const uint32_t*)(g_q + r1 + c * 16 + qp);
            qh[c][2] = *(const uint32_t*)(g_q + r0 + c * 16 + qp + 8);
            qh[c][3] = *(const uint32_t*)(g_q + r1 + c * 16 + qp + 8);
        }
    }

    float O[32];
#pragma unroll
    for (int i = 0; i < 32; i++) O[i] = 0.f;
    float lacc[4] = {0.f, 0.f, 0.f, 0.f};   // ones-mma accumulator (row sums)

    const int k_rhalf = (lane >> 4) << 3;
    const int k_csel  = (lane >> 3) & 1;
    const int k_i     = lane & 7;
    const int v_rhalf = ((lane >> 3) & 1) << 3;
    const int v_csel  = lane >> 4;

    const size_t mrow0 = (bS + qrow0 + grp) * S_;
    const size_t mrow1 = mrow0 + (size_t)8 * S_;

    auto fill = [&](int tt) {
        const int st = tt & 1;
        const uint32_t base = sb + st * AST;
        const size_t krow = bS + kbase + tt * 64;
#pragma unroll
        for (int idx = tid; idx < 512; idx += 128) {
            const int r = idx >> 3, g = idx & 7;
            const uint32_t off = (uint32_t)(r * 128 + ((g ^ (r & 7)) * 16));
            const size_t so = (krow + r) * DK_ + g * 8;
            cp16(base + off,        g_k + so);
            cp16(base + 8192 + off, g_v + so);
        }
        cp_commit();
    };

    // mask register prefetch (16 int2 = 32 regs), unrolled indices stay in regs
    int2 mreg[4][2][2];
    auto loadmask = [&](int tt) {
        const int kk0 = kbase + tt * 64;
#pragma unroll
        for (int nt2 = 0; nt2 < 4; nt2++)
#pragma unroll
            for (int half = 0; half < 2; half++) {
                const int col = kk0 + nt2 * 16 + half * 8 + qp;
                mreg[nt2][half][0] = *(const int2*)(mask + mrow0 + col);
                mreg[nt2][half][1] = *(const int2*)(mask + mrow1 + col);
            }
    };

    fill(0);
    loadmask(0);

    const int NT = S_ / NSPLIT / 64;   // 16 tiles
    for (int t = 0; t < NT; t++) {
        cp_wait<0>();
        __syncthreads();
        if (t + 1 < NT) fill(t + 1);

        const int st = t & 1;
        const uint32_t a_k = sb + st * AST;
        const uint32_t a_v = a_k + 8192;

        // ---- scores + softmax + P fragments  (scores arrive pre-scaled: p = 2^cc)
        uint32_t ph[4][4];
#pragma unroll
        for (int nt2 = 0; nt2 < 4; nt2++) {
            float cA[4] = {0.f, 0.f, 0.f, 0.f};
            float cB[4] = {0.f, 0.f, 0.f, 0.f};
#pragma unroll
            for (int c = 0; c < 4; c++) {
                const int row = nt2 * 16 + k_rhalf + k_i;
                const uint32_t off = (uint32_t)(row * 128 + (((c * 2 + k_csel) ^ (row & 7)) * 16));
                uint32_t bh[4];
                ldsm4(bh, a_k + off);
                mma_f16(cA, qh[c], bh[0], bh[1]);
                mma_f16(cB, qh[c], bh[2], bh[3]);
            }
#pragma unroll
            for (int half = 0; half < 2; half++) {
                float* cc = half ? cB : cA;
                const int2 mA = mreg[nt2][half][0];
                const int2 mB = mreg[nt2][half][1];
                const float p0 = ex2f(mA.x ? cc[0] : -127.f);
                const float p1 = ex2f(mA.y ? cc[1] : -127.f);
                const float p2 = ex2f(mB.x ? cc[2] : -127.f);
                const float p3 = ex2f(mB.y ? cc[3] : -127.f);
                ph[nt2][half * 2 + 0] = cvt_f16x2(p0, p1);
                ph[nt2][half * 2 + 1] = cvt_f16x2(p2, p3);
            }
            // l += P @ ones  (row sums, fp32 accumulate; all 8 cols identical)
            mma_f16(lacc, ph[nt2], ONES_H2, ONES_H2);
        }

        // prefetch next tile's mask; hidden under the PV mma block below
        if (t + 1 < NT) loadmask(t + 1);

        // ---- O += P @ V  (single pass; row-major V via ldmatrix.trans)
#pragma unroll
        for (int dt2 = 0; dt2 < 4; dt2++) {
            float* oA = &O[dt2 * 8];
            float* oB = &O[dt2 * 8 + 4];
#pragma unroll
            for (int kc = 0; kc < 4; kc++) {
                const int row = kc * 16 + v_rhalf + k_i;
                const uint32_t off = (uint32_t)(row * 128 + (((dt2 * 2 + v_csel) ^ (row & 7)) * 16));
                uint32_t bh[4];
                ldsm4t(bh, a_v + off);
                mma_f16(oA, ph[kc], bh[0], bh[1]);
                mma_f16(oB, ph[kc], bh[2], bh[3]);
            }
        }
        __syncthreads();   // all warps done with stage st before it is refilled
    }

    // ---- epilogue (lacc cols identical within quad; lacc[0]=row, lacc[2]=row+8)
    if ((lane & 3) == 0) {
        g_pl[sp][bS + qrow0 + grp]     = lacc[0];
        g_pl[sp][bS + qrow0 + grp + 8] = lacc[2];
    }
    float* dst0 = g_pacc[sp] + (bS + qrow0 + grp) * DK_;
    float* dst1 = dst0 + 8 * DK_;
#pragma unroll
    for (int dt = 0; dt < 8; dt++) {
        const int col = dt * 8 + qp;
        *(float2*)(dst0 + col) = make_float2(O[dt * 4 + 0], O[dt * 4 + 1]);
        *(float2*)(dst1 + col) = make_float2(O[dt * 4 + 2], O[dt * 4 + 3]);
    }
}

// ===========================================================================
// Merge the kv-splits: y = sum(acc) / sum(l)
// ===========================================================================
__global__ __launch_bounds__(256)
void merge_kernel(float* __restrict__ out)
{
    const int idx = blockIdx.x * 256 + threadIdx.x;
    const int r = idx >> 6;
    float l = 0.f, a = 0.f;
#pragma unroll
    for (int s = 0; s < NSPLIT; s++) {
        l += g_pl[s][r];
        a += g_pacc[s][idx];
    }
    out[idx] = a / l;
}

// ===========================================================================
extern "C" void kernel_launch(void* const* d_in, const int* in_sizes, int n_in,
                              void* d_out, int out_size)
{
    const float* Q    = (const float*)d_in[0];
    const float* K    = (const float*)d_in[1];
    const float* V    = (const float*)d_in[2];
    const int*   mask = (const int*)  d_in[3];
    const float* Wq   = (const float*)d_in[4];
    const float* bq   = (const float*)d_in[5];
    const float* Wk   = (const float*)d_in[6];
    const float* bk   = (const float*)d_in[7];
    const float* Wv   = (const float*)d_in[8];
    const float* bv   = (const float*)d_in[9];
    float* out = (float*)d_out;

    prep_w<<<dim3(DK_, 3), 256>>>(Wq, Wk, Wv);

    cudaFuncSetAttribute(proj_tc, cudaFuncAttributeMaxDynamicSharedMemorySize, PSM_TOTAL);
    proj_tc<<<dim3((B_ * S_) / 64, 3), 128, PSM_TOTAL>>>(Q, K, V, bq, bk, bv);

    cudaFuncSetAttribute(attn_mma_kernel,
                         cudaFuncAttributeMaxDynamicSharedMemorySize, ASM_TOTAL);
    attn_mma_kernel<<<dim3(S_ / 64, B_, NSPLIT), 128, ASM_TOTAL>>>(mask);

    merge_kernel<<<(B_ * S_ * DK_) / 256, 256>>>(out);
}

// round 14
// speedup vs baseline: 6.5568x; 1.4565x over previous
#include <cuda_runtime.h>
#include <cuda_bf16.h>
#include <cuda_fp16.h>
#include <cstdint>

#define B_   2
#define S_   4096
#define DM_  1024
#define DK_  64
#define NSPLIT 4

// ===========================================================================
// Scratch (__device__ globals per allocation rules)
// ===========================================================================
__device__ __half g_q [B_ * S_ * DK_];           // q * 0.125*log2e, fp16
__device__ __half g_k [B_ * S_ * DK_];           // k single fp16
__device__ __half g_v [B_ * S_ * DK_];           // v single fp16 (row-major)
__device__ __nv_bfloat16 g_wh[3 * DK_ * DM_];    // W bf16 hi/lo (proj stays 3-pass)
__device__ __nv_bfloat16 g_wl[3 * DK_ * DM_];
__device__ float g_pacc[NSPLIT][B_ * S_ * DK_];  // per-split unnormalized O
__device__ float g_pl[NSPLIT][B_ * S_];          // per-split softmax denominators

__device__ __forceinline__ uint32_t smem_to_u32(const void* p) {
    uint32_t a;
    asm("{ .reg .u64 t; cvta.to.shared.u64 t, %1; cvt.u32.u64 %0, t; }" : "=r"(a) : "l"(p));
    return a;
}
__device__ __forceinline__ uint32_t pack_bf16(__nv_bfloat16 a, __nv_bfloat16 b) {
    return (uint32_t)__bfloat16_as_ushort(a) | ((uint32_t)__bfloat16_as_ushort(b) << 16);
}
__device__ __forceinline__ void split2(float a, float b, uint32_t& h, uint32_t& l) {
    const __nv_bfloat16 ha = __float2bfloat16(a);
    const __nv_bfloat16 hb = __float2bfloat16(b);
    h = pack_bf16(ha, hb);
    l = pack_bf16(__float2bfloat16(a - __bfloat162float(ha)),
                  __float2bfloat16(b - __bfloat162float(hb)));
}
// fast hi/lo split: hi = truncated top-16 bits (PRMT pack), lo = rn(residual)
__device__ __forceinline__ void split2_fast(float a, float b, uint32_t& h, uint32_t& l) {
    const uint32_t ia = __float_as_uint(a), ib = __float_as_uint(b);
    asm("prmt.b32 %0, %1, %2, 0x7632;" : "=r"(h) : "r"(ia), "r"(ib));
    const float ra = a - __uint_as_float(ia & 0xFFFF0000u);
    const float rb = b - __uint_as_float(ib & 0xFFFF0000u);
    asm("cvt.rn.bf16x2.f32 %0, %1, %2;" : "=r"(l) : "f"(rb), "f"(ra));
}
__device__ __forceinline__ uint32_t pack_h2(__half a, __half b) {
    const __half2 v = __halves2half2(a, b);   // a -> low
    return *(const uint32_t*)&v;
}
__device__ __forceinline__ float ex2f(float x) {
    float y;
    asm("ex2.approx.f32 %0, %1;" : "=f"(y) : "f"(x));
    return y;
}
__device__ __forceinline__ uint32_t cvt_f16x2(float lo, float hi) {
    uint32_t d;
    asm("cvt.rn.f16x2.f32 %0, %1, %2;" : "=r"(d) : "f"(hi), "f"(lo));   // lo -> low half
    return d;
}
__device__ __forceinline__ void mma_bf16(float c[4], const uint32_t a[4],
                                         uint32_t b0, uint32_t b1) {
    asm volatile("mma.sync.aligned.m16n8k16.row.col.f32.bf16.bf16.f32 "
        "{%0,%1,%2,%3}, {%4,%5,%6,%7}, {%8,%9}, {%0,%1,%2,%3};"
        : "+f"(c[0]), "+f"(c[1]), "+f"(c[2]), "+f"(c[3])
        : "r"(a[0]), "r"(a[1]), "r"(a[2]), "r"(a[3]), "r"(b0), "r"(b1));
}
__device__ __forceinline__ void mma_f16(float c[4], const uint32_t a[4],
                                        uint32_t b0, uint32_t b1) {
    asm volatile("mma.sync.aligned.m16n8k16.row.col.f32.f16.f16.f32 "
        "{%0,%1,%2,%3}, {%4,%5,%6,%7}, {%8,%9}, {%0,%1,%2,%3};"
        : "+f"(c[0]), "+f"(c[1]), "+f"(c[2]), "+f"(c[3])
        : "r"(a[0]), "r"(a[1]), "r"(a[2]), "r"(a[3]), "r"(b0), "r"(b1));
}
__device__ __forceinline__ void ldsm4(uint32_t r[4], uint32_t addr) {
    asm volatile("ldmatrix.sync.aligned.m8n8.x4.shared.b16 {%0,%1,%2,%3}, [%4];"
        : "=r"(r[0]), "=r"(r[1]), "=r"(r[2]), "=r"(r[3]) : "r"(addr));
}
__device__ __forceinline__ void ldsm4t(uint32_t r[4], uint32_t addr) {
    asm volatile("ldmatrix.sync.aligned.m8n8.x4.trans.shared.b16 {%0,%1,%2,%3}, [%4];"
        : "=r"(r[0]), "=r"(r[1]), "=r"(r[2]), "=r"(r[3]) : "r"(addr));
}
__device__ __forceinline__ void cp16(uint32_t smem, const void* g) {
    asm volatile("cp.async.cg.shared.global [%0], [%1], 16;" :: "r"(smem), "l"(g));
}
__device__ __forceinline__ void cp_commit() {
    asm volatile("cp.async.commit_group;");
}
template <int N>
__device__ __forceinline__ void cp_wait() {
    asm volatile("cp.async.wait_group %0;" :: "n"(N));
}

// ===========================================================================
// prep_w: convert Wq/Wk/Wv fp32 -> bf16 hi/lo once.  grid (64, 3) x 256
// ===========================================================================
__global__ __launch_bounds__(256)
void prep_w(const float* __restrict__ Wq, const float* __restrict__ Wk,
            const float* __restrict__ Wv)
{
    const int which = blockIdx.y;
    const float* W = (which == 0) ? Wq : (which == 1) ? Wk : Wv;
    const int n = blockIdx.x;
    const int col = threadIdx.x * 4;
    const float4 v = *(const float4*)(W + n * DM_ + col);
    uint32_t h0, l0, h1, l1;
    split2(v.x, v.y, h0, l0);
    split2(v.z, v.w, h1, l1);
    const size_t off = (size_t)which * DK_ * DM_ + n * DM_ + col;
    *(uint2*)(g_wh + off) = make_uint2(h0, h1);
    *(uint2*)(g_wl + off) = make_uint2(l0, l1);
}

// ===========================================================================
// proj_tc: C[8192x64] = A @ W^T + bias, bf16 hi/lo 3-pass mma, pipelined.
// Epilogue: single-fp16 emit; q pre-scaled by 0.125*log2(e).
// CTA: 64 rows (4 warps x 16), K-chunks of 64.  grid (128, 3) x 128.
// ===========================================================================
#define PSM_AH 0
#define PSM_AL 8192
#define PSM_W  16384          /* + stage*16384 ; WH +0, WL +8192 */
#define PSM_TOTAL 49152
#define QSCALE 0.1803368801f  /* 0.125 * log2(e) */

__global__ __launch_bounds__(128)
void proj_tc(const float* __restrict__ Qin, const float* __restrict__ Kin,
             const float* __restrict__ Vin,
             const float* __restrict__ bq, const float* __restrict__ bk,
             const float* __restrict__ bv)
{
    extern __shared__ char ps[];
    const uint32_t sb = smem_to_u32(ps);

    const int which = blockIdx.y;
    const int tid  = threadIdx.x;
    const int wid  = tid >> 5;
    const int lane = tid & 31;

    const float* A    = (which == 0) ? Qin : (which == 1) ? Kin : Vin;
    const float* bias = (which == 0) ? bq  : (which == 1) ? bk  : bv;
    __half* D         = (which == 0) ? g_q : (which == 1) ? g_k : g_v;
    const float osc   = (which == 0) ? QSCALE : 1.0f;
    const __nv_bfloat16* Wh = g_wh + (size_t)which * DK_ * DM_;
    const __nv_bfloat16* Wl = g_wl + (size_t)which * DK_ * DM_;

    const int m0 = blockIdx.x * 64;

    float c[8][4];
#pragma unroll
    for (int i = 0; i < 8; i++)
#pragma unroll
        for (int j = 0; j < 4; j++) c[i][j] = 0.f;

    const int arow  = wid * 16 + ((lane >> 3) & 1) * 8 + (lane & 7);
    const int acsel = lane >> 4;
    const int brow  = ((lane >> 4) << 3) + (lane & 7);
    const int bcsel = (lane >> 3) & 1;

    const int pr[4] = { (tid + 0)   >> 3, (tid + 128) >> 3,
                        (tid + 256) >> 3, (tid + 384) >> 3 };
    const int pg    = tid & 7;

    auto fillW = [&](int kc, int st) {
        const uint32_t wb = sb + PSM_W + st * 16384;
#pragma unroll
        for (int idx = tid; idx < 512; idx += 128) {
            const int n = idx >> 3, g = idx & 7;
            const uint32_t off = (uint32_t)(n * 128 + ((g ^ (n & 7)) * 16));
            cp16(wb + off,        Wh + (size_t)n * DM_ + kc * 64 + g * 8);
            cp16(wb + 8192 + off, Wl + (size_t)n * DM_ + kc * 64 + g * 8);
        }
        cp_commit();
    };

    float4 aPre[8];
#pragma unroll
    for (int i = 0; i < 4; i++) {
        const float* src = A + (size_t)(m0 + pr[i]) * DM_ + pg * 8;
        aPre[2 * i]     = *(const float4*)src;
        aPre[2 * i + 1] = *(const float4*)(src + 4);
    }
    fillW(0, 0);

    for (int kc = 0; kc < 16; kc++) {
        cp_wait<0>();
        __syncthreads();
#pragma unroll
        for (int i = 0; i < 4; i++) {
            uint4 hv, lv;
            split2_fast(aPre[2 * i].x,     aPre[2 * i].y,     hv.x, lv.x);
            split2_fast(aPre[2 * i].z,     aPre[2 * i].w,     hv.y, lv.y);
            split2_fast(aPre[2 * i + 1].x, aPre[2 * i + 1].y, hv.z, lv.z);
            split2_fast(aPre[2 * i + 1].z, aPre[2 * i + 1].w, hv.w, lv.w);
            const uint32_t off = (uint32_t)(pr[i] * 128 + ((pg ^ (pr[i] & 7)) * 16));
            *(uint4*)(ps + PSM_AH + off) = hv;
            *(uint4*)(ps + PSM_AL + off) = lv;
        }
        if (kc < 15) {
#pragma unroll
            for (int i = 0; i < 4; i++) {
                const float* src = A + (size_t)(m0 + pr[i]) * DM_ + (kc + 1) * 64 + pg * 8;
                aPre[2 * i]     = *(const float4*)src;
                aPre[2 * i + 1] = *(const float4*)(src + 4);
            }
            fillW(kc + 1, (kc + 1) & 1);
        }
        __syncthreads();

        const uint32_t a_Ah = sb + PSM_AH;
        const uint32_t a_Al = sb + PSM_AL;
        const uint32_t a_Wh = sb + PSM_W + (kc & 1) * 16384;
        const uint32_t a_Wl = a_Wh + 8192;

        uint32_t ah[4][4], al[4][4];
#pragma unroll
        for (int k4 = 0; k4 < 4; k4++) {
            const int ch = k4 * 2 + acsel;
            const uint32_t off = (uint32_t)(arow * 128 + ((ch ^ (arow & 7)) * 16));
            ldsm4(ah[k4], a_Ah + off);
            ldsm4(al[k4], a_Al + off);
        }
#pragma unroll
        for (int nt = 0; nt < 4; nt++) {
            const int row = nt * 16 + brow;
#pragma unroll
            for (int k4 = 0; k4 < 4; k4++) {
                const int ch = k4 * 2 + bcsel;
                const uint32_t off = (uint32_t)(row * 128 + ((ch ^ (row & 7)) * 16));
                uint32_t wh[4], wl[4];
                ldsm4(wh, a_Wh + off);
                ldsm4(wl, a_Wl + off);
                mma_bf16(c[nt * 2],     ah[k4], wh[0], wh[1]);
                mma_bf16(c[nt * 2],     ah[k4], wl[0], wl[1]);
                mma_bf16(c[nt * 2],     al[k4], wh[0], wh[1]);
                mma_bf16(c[nt * 2 + 1], ah[k4], wh[2], wh[3]);
                mma_bf16(c[nt * 2 + 1], ah[k4], wl[2], wl[3]);
                mma_bf16(c[nt * 2 + 1], al[k4], wh[2], wh[3]);
            }
        }
    }

    // epilogue: bias (+ q pre-scale) + single fp16 emit
    const int grp = lane >> 2;
    const int qp  = (lane & 3) * 2;
    const size_t row0 = (size_t)(m0 + wid * 16 + grp);
    const size_t row1 = row0 + 8;
#pragma unroll
    for (int nt = 0; nt < 8; nt++) {
        const int col = nt * 8 + qp;
        const float b0 = bias[col], b1 = bias[col + 1];
        *(uint32_t*)(D + row0 * DK_ + col) =
            pack_h2(__float2half_rn((c[nt][0] + b0) * osc),
                    __float2half_rn((c[nt][1] + b1) * osc));
        *(uint32_t*)(D + row1 * DK_ + col) =
            pack_h2(__float2half_rn((c[nt][2] + b0) * osc),
                    __float2half_rn((c[nt][3] + b1) * osc));
    }
}

// ===========================================================================
// attention: 64-q CTA (4 warps x 16 rows), 64-key tiles, kv-split 4.
// Single-pass fp16; ex2 softmax; l via ones-mma.
// K/V double-buffered (2 x 16K); mask SINGLE 17K cp.async buffer refilled
// after softmax each tile.  smem 50176 -> 4 CTAs/SM -> single wave.
// ===========================================================================
#define KVST      16384        /* per K/V stage */
#define ASM_MASK  32768        /* single mask buffer, stride 272 */
#define ASM_TOTAL 50176
#define ONES_H2   0x3C003C00u

__global__ __launch_bounds__(128, 4)
void attn_mma_kernel(const int* __restrict__ mask)
{
    extern __shared__ char sm[];
    const uint32_t sb = smem_to_u32(sm);

    const int tid  = threadIdx.x;
    const int wid  = tid >> 5;
    const int lane = tid & 31;
    const int grp  = lane >> 2;
    const int qp   = (lane & 3) * 2;

    const int b     = blockIdx.y;
    const int sp    = blockIdx.z;
    const int q0    = blockIdx.x * 64;
    const int kbase = sp * (S_ / NSPLIT);
    const int qrow0 = q0 + wid * 16;
    const size_t bS = (size_t)b * S_;

    // Q fragments (single fp16, pre-scaled) from global, A-frag m16k16 layout
    uint32_t qh[4][4];
    {
        const size_t r0 = (bS + qrow0 + grp) * DK_;
        const size_t r1 = r0 + 8 * DK_;
#pragma unroll
        for (int c = 0; c < 4; c++) {
            qh[c][0] = *(const uint32_t*)(g_q + r0 + c * 16 + qp);
            qh[c][1] = *(const uint32_t*)(g_q + r1 + c * 16 + qp);
            qh[c][2] = *(const uint32_t*)(g_q + r0 + c * 16 + qp + 8);
            qh[c][3] = *(const uint32_t*)(g_q + r1 + c * 16 + qp + 8);
        }
    }

    float O[32];
#pragma unroll
    for (int i = 0; i < 32; i++) O[i] = 0.f;
    float lacc[4] = {0.f, 0.f, 0.f, 0.f};   // ones-mma accumulator (row sums)

    const int k_rhalf = (lane >> 4) << 3;
    const int k_csel  = (lane >> 3) & 1;
    const int k_i     = lane & 7;
    const int v_rhalf = ((lane >> 3) & 1) << 3;
    const int v_csel  = lane >> 4;

    auto fill = [&](int tt) {     // K/V only, double-buffered
        const int st = tt & 1;
        const uint32_t base = sb + st * KVST;
        const size_t krow = bS + kbase + tt * 64;
#pragma unroll
        for (int idx = tid; idx < 512; idx += 128) {
            const int r = idx >> 3, g = idx & 7;
            const uint32_t off = (uint32_t)(r * 128 + ((g ^ (r & 7)) * 16));
            const size_t so = (krow + r) * DK_ + g * 8;
            cp16(base + off,        g_k + so);
            cp16(base + 8192 + off, g_v + so);
        }
        cp_commit();
    };
    auto maskfill = [&](int tt) { // single buffer
        const int kk0 = kbase + tt * 64;
#pragma unroll
        for (int idx = tid; idx < 1024; idx += 128) {
            const int r = idx >> 4, c = idx & 15;
            cp16(sb + ASM_MASK + r * 272 + c * 16,
                 mask + (bS + q0 + r) * S_ + kk0 + c * 4);
        }
        cp_commit();
    };

    fill(0);
    maskfill(0);

    const int NT = S_ / NSPLIT / 64;   // 16 tiles
    for (int t = 0; t < NT; t++) {
        cp_wait<0>();
        __syncthreads();
        if (t + 1 < NT) fill(t + 1);

        const int st = t & 1;
        const uint32_t a_k = sb + st * KVST;
        const uint32_t a_v = a_k + 8192;
        const char* mptr = sm + ASM_MASK;

        // ---- scores + softmax + P fragments  (scores arrive pre-scaled: p = 2^cc)
        uint32_t ph[4][4];
#pragma unroll
        for (int nt2 = 0; nt2 < 4; nt2++) {
            float cA[4] = {0.f, 0.f, 0.f, 0.f};
            float cB[4] = {0.f, 0.f, 0.f, 0.f};
#pragma unroll
            for (int c = 0; c < 4; c++) {
                const int row = nt2 * 16 + k_rhalf + k_i;
                const uint32_t off = (uint32_t)(row * 128 + (((c * 2 + k_csel) ^ (row & 7)) * 16));
                uint32_t bh[4];
                ldsm4(bh, a_k + off);
                mma_f16(cA, qh[c], bh[0], bh[1]);
                mma_f16(cB, qh[c], bh[2], bh[3]);
            }
#pragma unroll
            for (int half = 0; half < 2; half++) {
                float* cc = half ? cB : cA;
                const int colw = nt2 * 16 + half * 8 + qp;
                const int2 mA = *(const int2*)(mptr + (wid * 16 + grp) * 272 + colw * 4);
                const int2 mB = *(const int2*)(mptr + (wid * 16 + grp + 8) * 272 + colw * 4);
                const float p0 = ex2f(mA.x ? cc[0] : -127.f);
                const float p1 = ex2f(mA.y ? cc[1] : -127.f);
                const float p2 = ex2f(mB.x ? cc[2] : -127.f);
                const float p3 = ex2f(mB.y ? cc[3] : -127.f);
                ph[nt2][half * 2 + 0] = cvt_f16x2(p0, p1);
                ph[nt2][half * 2 + 1] = cvt_f16x2(p2, p3);
            }
            // l += P @ ones  (row sums, fp32 accumulate; all 8 cols identical)
            mma_f16(lacc, ph[nt2], ONES_H2, ONES_H2);
        }

        // all warps done reading mask buffer -> refill it for t+1, hidden under PV
        __syncthreads();
        if (t + 1 < NT) maskfill(t + 1);

        // ---- O += P @ V  (single pass; row-major V via ldmatrix.trans)
#pragma unroll
        for (int dt2 = 0; dt2 < 4; dt2++) {
            float* oA = &O[dt2 * 8];
            float* oB = &O[dt2 * 8 + 4];
#pragma unroll
            for (int kc = 0; kc < 4; kc++) {
                const int row = kc * 16 + v_rhalf + k_i;
                const uint32_t off = (uint32_t)(row * 128 + (((dt2 * 2 + v_csel) ^ (row & 7)) * 16));
                uint32_t bh[4];
                ldsm4t(bh, a_v + off);
                mma_f16(oA, ph[kc], bh[0], bh[1]);
                mma_f16(oB, ph[kc], bh[2], bh[3]);
            }
        }
    }

    // ---- epilogue (lacc cols identical within quad; lacc[0]=row, lacc[2]=row+8)
    if ((lane & 3) == 0) {
        g_pl[sp][bS + qrow0 + grp]     = lacc[0];
        g_pl[sp][bS + qrow0 + grp + 8] = lacc[2];
    }
    float* dst0 = g_pacc[sp] + (bS + qrow0 + grp) * DK_;
    float* dst1 = dst0 + 8 * DK_;
#pragma unroll
    for (int dt = 0; dt < 8; dt++) {
        const int col = dt * 8 + qp;
        *(float2*)(dst0 + col) = make_float2(O[dt * 4 + 0], O[dt * 4 + 1]);
        *(float2*)(dst1 + col) = make_float2(O[dt * 4 + 2], O[dt * 4 + 3]);
    }
}

// ===========================================================================
// Merge the kv-splits: y = sum(acc) / sum(l)
// ===========================================================================
__global__ __launch_bounds__(256)
void merge_kernel(float* __restrict__ out)
{
    const int idx = blockIdx.x * 256 + threadIdx.x;
    const int r = idx >> 6;
    float l = 0.f, a = 0.f;
#pragma unroll
    for (int s = 0; s < NSPLIT; s++) {
        l += g_pl[s][r];
        a += g_pacc[s][idx];
    }
    out[idx] = a / l;
}

// ===========================================================================
extern "C" void kernel_launch(void* const* d_in, const int* in_sizes, int n_in,
                              void* d_out, int out_size)
{
    const float* Q    = (const float*)d_in[0];
    const float* K    = (const float*)d_in[1];
    const float* V    = (const float*)d_in[2];
    const int*   mask = (const int*)  d_in[3];
    const float* Wq   = (const float*)d_in[4];
    const float* bq   = (const float*)d_in[5];
    const float* Wk   = (const float*)d_in[6];
    const float* bk   = (const float*)d_in[7];
    const float* Wv   = (const float*)d_in[8];
    const float* bv   = (const float*)d_in[9];
    float* out = (float*)d_out;

    prep_w<<<dim3(DK_, 3), 256>>>(Wq, Wk, Wv);

    cudaFuncSetAttribute(proj_tc, cudaFuncAttributeMaxDynamicSharedMemorySize, PSM_TOTAL);
    proj_tc<<<dim3((B_ * S_) / 64, 3), 128, PSM_TOTAL>>>(Q, K, V, bq, bk, bv);

    cudaFuncSetAttribute(attn_mma_kernel,
                         cudaFuncAttributeMaxDynamicSharedMemorySize, ASM_TOTAL);
    attn_mma_kernel<<<dim3(S_ / 64, B_, NSPLIT), 128, ASM_TOTAL>>>(mask);

    merge_kernel<<<(B_ * S_ * DK_) / 256, 256>>>(out);
}

// round 16
// speedup vs baseline: 7.2705x; 1.1088x over previous
#include <cuda_runtime.h>
#include <cuda_bf16.h>
#include <cuda_fp16.h>
#include <cstdint>

#define B_   2
#define S_   4096
#define DM_  1024
#define DK_  64
#define NSPLIT 4

// ===========================================================================
// Scratch (__device__ globals per allocation rules)
// ===========================================================================
__device__ __half g_q [B_ * S_ * DK_];           // q * 0.125*log2e, fp16
__device__ __half g_k [B_ * S_ * DK_];           // k single fp16
__device__ __half g_v [B_ * S_ * DK_];           // v single fp16 (row-major)
__device__ __half g_w [3 * DK_ * DM_];           // W single fp16 (2-pass proj)
__device__ float g_pacc[NSPLIT][B_ * S_ * DK_];  // per-split unnormalized O
__device__ float g_pl[NSPLIT][B_ * S_];          // per-split softmax denominators

__device__ __forceinline__ uint32_t smem_to_u32(const void* p) {
    uint32_t a;
    asm("{ .reg .u64 t; cvta.to.shared.u64 t, %1; cvt.u32.u64 %0, t; }" : "=r"(a) : "l"(p));
    return a;
}
__device__ __forceinline__ uint32_t pack_h2(__half a, __half b) {
    const __half2 v = __halves2half2(a, b);   // a -> low
    return *(const uint32_t*)&v;
}
// exact fp16 hi/lo split of two fp32 values (hi = rn(x), lo = rn(x - hi))
__device__ __forceinline__ void split2h(float a, float b, uint32_t& h, uint32_t& l) {
    const __half ha = __float2half_rn(a);
    const __half hb = __float2half_rn(b);
    h = pack_h2(ha, hb);
    l = pack_h2(__float2half_rn(a - __half2float(ha)),
                __float2half_rn(b - __half2float(hb)));
}
__device__ __forceinline__ float ex2f(float x) {
    float y;
    asm("ex2.approx.f32 %0, %1;" : "=f"(y) : "f"(x));
    return y;
}
__device__ __forceinline__ uint32_t cvt_f16x2(float lo, float hi) {
    uint32_t d;
    asm("cvt.rn.f16x2.f32 %0, %1, %2;" : "=r"(d) : "f"(hi), "f"(lo));   // lo -> low half
    return d;
}
__device__ __forceinline__ void mma_f16(float c[4], const uint32_t a[4],
                                        uint32_t b0, uint32_t b1) {
    asm volatile("mma.sync.aligned.m16n8k16.row.col.f32.f16.f16.f32 "
        "{%0,%1,%2,%3}, {%4,%5,%6,%7}, {%8,%9}, {%0,%1,%2,%3};"
        : "+f"(c[0]), "+f"(c[1]), "+f"(c[2]), "+f"(c[3])
        : "r"(a[0]), "r"(a[1]), "r"(a[2]), "r"(a[3]), "r"(b0), "r"(b1));
}
__device__ __forceinline__ void ldsm4(uint32_t r[4], uint32_t addr) {
    asm volatile("ldmatrix.sync.aligned.m8n8.x4.shared.b16 {%0,%1,%2,%3}, [%4];"
        : "=r"(r[0]), "=r"(r[1]), "=r"(r[2]), "=r"(r[3]) : "r"(addr));
}
__device__ __forceinline__ void ldsm4t(uint32_t r[4], uint32_t addr) {
    asm volatile("ldmatrix.sync.aligned.m8n8.x4.trans.shared.b16 {%0,%1,%2,%3}, [%4];"
        : "=r"(r[0]), "=r"(r[1]), "=r"(r[2]), "=r"(r[3]) : "r"(addr));
}
__device__ __forceinline__ void cp16(uint32_t smem, const void* g) {
    asm volatile("cp.async.cg.shared.global [%0], [%1], 16;" :: "r"(smem), "l"(g));
}
__device__ __forceinline__ void cp_commit() {
    asm volatile("cp.async.commit_group;");
}
template <int N>
__device__ __forceinline__ void cp_wait() {
    asm volatile("cp.async.wait_group %0;" :: "n"(N));
}

// ===========================================================================
// prep_w: convert Wq/Wk/Wv fp32 -> single fp16 once.  grid (64, 3) x 256
// ===========================================================================
__global__ __launch_bounds__(256)
void prep_w(const float* __restrict__ Wq, const float* __restrict__ Wk,
            const float* __restrict__ Wv)
{
    const int which = blockIdx.y;
    const float* W = (which == 0) ? Wq : (which == 1) ? Wk : Wv;
    const int n = blockIdx.x;
    const int col = threadIdx.x * 4;
    const float4 v = *(const float4*)(W + n * DM_ + col);
    const size_t off = (size_t)which * DK_ * DM_ + n * DM_ + col;
    *(uint2*)(g_w + off) = make_uint2(
        pack_h2(__float2half_rn(v.x), __float2half_rn(v.y)),
        pack_h2(__float2half_rn(v.z), __float2half_rn(v.w)));
}

// ===========================================================================
// proj_tc: C[8192x64] = A @ W^T + bias, 2-pass fp16 (A hi/lo exact, W rounded).
// Epilogue: single-fp16 emit; q pre-scaled by 0.125*log2(e).
// CTA: 64 rows (4 warps x 16), K-chunks of 64.  grid (128, 3) x 128.
// smem: A_h 8K | A_l 8K | W[2] 8K each = 32K
// ===========================================================================
#define PSM_AH 0
#define PSM_AL 8192
#define PSM_W  16384          /* + stage*8192 */
#define PSM_TOTAL 32768
#define QSCALE 0.1803368801f  /* 0.125 * log2(e) */

__global__ __launch_bounds__(128)
void proj_tc(const float* __restrict__ Qin, const float* __restrict__ Kin,
             const float* __restrict__ Vin,
             const float* __restrict__ bq, const float* __restrict__ bk,
             const float* __restrict__ bv)
{
    extern __shared__ char ps[];
    const uint32_t sb = smem_to_u32(ps);

    const int which = blockIdx.y;
    const int tid  = threadIdx.x;
    const int wid  = tid >> 5;
    const int lane = tid & 31;

    const float* A    = (which == 0) ? Qin : (which == 1) ? Kin : Vin;
    const float* bias = (which == 0) ? bq  : (which == 1) ? bk  : bv;
    __half* D         = (which == 0) ? g_q : (which == 1) ? g_k : g_v;
    const float osc   = (which == 0) ? QSCALE : 1.0f;
    const __half* Wp  = g_w + (size_t)which * DK_ * DM_;

    const int m0 = blockIdx.x * 64;

    float c[8][4];
#pragma unroll
    for (int i = 0; i < 8; i++)
#pragma unroll
        for (int j = 0; j < 4; j++) c[i][j] = 0.f;

    const int arow  = wid * 16 + ((lane >> 3) & 1) * 8 + (lane & 7);
    const int acsel = lane >> 4;
    const int brow  = ((lane >> 4) << 3) + (lane & 7);
    const int bcsel = (lane >> 3) & 1;

    const int pr[4] = { (tid + 0)   >> 3, (tid + 128) >> 3,
                        (tid + 256) >> 3, (tid + 384) >> 3 };
    const int pg    = tid & 7;

    auto fillW = [&](int kc, int st) {
        const uint32_t wb = sb + PSM_W + st * 8192;
#pragma unroll
        for (int idx = tid; idx < 512; idx += 128) {
            const int n = idx >> 3, g = idx & 7;
            const uint32_t off = (uint32_t)(n * 128 + ((g ^ (n & 7)) * 16));
            cp16(wb + off, Wp + (size_t)n * DM_ + kc * 64 + g * 8);
        }
        cp_commit();
    };

    float4 aPre[8];
#pragma unroll
    for (int i = 0; i < 4; i++) {
        const float* src = A + (size_t)(m0 + pr[i]) * DM_ + pg * 8;
        aPre[2 * i]     = *(const float4*)src;
        aPre[2 * i + 1] = *(const float4*)(src + 4);
    }
    fillW(0, 0);

    for (int kc = 0; kc < 16; kc++) {
        cp_wait<0>();
        __syncthreads();
#pragma unroll
        for (int i = 0; i < 4; i++) {
            uint4 hv, lv;
            split2h(aPre[2 * i].x,     aPre[2 * i].y,     hv.x, lv.x);
            split2h(aPre[2 * i].z,     aPre[2 * i].w,     hv.y, lv.y);
            split2h(aPre[2 * i + 1].x, aPre[2 * i + 1].y, hv.z, lv.z);
            split2h(aPre[2 * i + 1].z, aPre[2 * i + 1].w, hv.w, lv.w);
            const uint32_t off = (uint32_t)(pr[i] * 128 + ((pg ^ (pr[i] & 7)) * 16));
            *(uint4*)(ps + PSM_AH + off) = hv;
            *(uint4*)(ps + PSM_AL + off) = lv;
        }
        if (kc < 15) {
#pragma unroll
            for (int i = 0; i < 4; i++) {
                const float* src = A + (size_t)(m0 + pr[i]) * DM_ + (kc + 1) * 64 + pg * 8;
                aPre[2 * i]     = *(const float4*)src;
                aPre[2 * i + 1] = *(const float4*)(src + 4);
            }
            fillW(kc + 1, (kc + 1) & 1);
        }
        __syncthreads();

        const uint32_t a_Ah = sb + PSM_AH;
        const uint32_t a_Al = sb + PSM_AL;
        const uint32_t a_W  = sb + PSM_W + (kc & 1) * 8192;

        uint32_t ah[4][4], al[4][4];
#pragma unroll
        for (int k4 = 0; k4 < 4; k4++) {
            const int ch = k4 * 2 + acsel;
            const uint32_t off = (uint32_t)(arow * 128 + ((ch ^ (arow & 7)) * 16));
            ldsm4(ah[k4], a_Ah + off);
            ldsm4(al[k4], a_Al + off);
        }
#pragma unroll
        for (int nt = 0; nt < 4; nt++) {
            const int row = nt * 16 + brow;
#pragma unroll
            for (int k4 = 0; k4 < 4; k4++) {
                const int ch = k4 * 2 + bcsel;
                const uint32_t off = (uint32_t)(row * 128 + ((ch ^ (row & 7)) * 16));
                uint32_t wh[4];
                ldsm4(wh, a_W + off);
                mma_f16(c[nt * 2],     ah[k4], wh[0], wh[1]);
                mma_f16(c[nt * 2],     al[k4], wh[0], wh[1]);
                mma_f16(c[nt * 2 + 1], ah[k4], wh[2], wh[3]);
                mma_f16(c[nt * 2 + 1], al[k4], wh[2], wh[3]);
            }
        }
    }

    // epilogue: bias (+ q pre-scale) + single fp16 emit
    const int grp = lane >> 2;
    const int qp  = (lane & 3) * 2;
    const size_t row0 = (size_t)(m0 + wid * 16 + grp);
    const size_t row1 = row0 + 8;
#pragma unroll
    for (int nt = 0; nt < 8; nt++) {
        const int col = nt * 8 + qp;
        const float b0 = bias[col], b1 = bias[col + 1];
        *(uint32_t*)(D + row0 * DK_ + col) =
            pack_h2(__float2half_rn((c[nt][0] + b0) * osc),
                    __float2half_rn((c[nt][1] + b1) * osc));
        *(uint32_t*)(D + row1 * DK_ + col) =
            pack_h2(__float2half_rn((c[nt][2] + b0) * osc),
                    __float2half_rn((c[nt][3] + b1) * osc));
    }
}

// ===========================================================================
// attention: 64-q CTA (4 warps x 16 rows), 64-key tiles, kv-split 4.
// Single-pass fp16; ex2 softmax; l via ones-mma.
// K/V double-buffered (2 x 16K); mask SINGLE 17K cp.async buffer refilled
// after softmax each tile.  smem 50176 -> 4 CTAs/SM -> single wave.
// ===========================================================================
#define KVST      16384        /* per K/V stage */
#define ASM_MASK  32768        /* single mask buffer, stride 272 */
#define ASM_TOTAL 50176
#define ONES_H2   0x3C003C00u

__global__ __launch_bounds__(128, 4)
void attn_mma_kernel(const int* __restrict__ mask)
{
    extern __shared__ char sm[];
    const uint32_t sb = smem_to_u32(sm);

    const int tid  = threadIdx.x;
    const int wid  = tid >> 5;
    const int lane = tid & 31;
    const int grp  = lane >> 2;
    const int qp   = (lane & 3) * 2;

    const int b     = blockIdx.y;
    const int sp    = blockIdx.z;
    const int q0    = blockIdx.x * 64;
    const int kbase = sp * (S_ / NSPLIT);
    const int qrow0 = q0 + wid * 16;
    const size_t bS = (size_t)b * S_;

    // Q fragments (single fp16, pre-scaled) from global, A-frag m16k16 layout
    uint32_t qh[4][4];
    {
        const size_t r0 = (bS + qrow0 + grp) * DK_;
        const size_t r1 = r0 + 8 * DK_;
#pragma unroll
        for (int c = 0; c < 4; c++) {
            qh[c][0] = *(const uint32_t*)(g_q + r0 + c * 16 + qp);
            qh[c][1] = *(const uint32_t*)(g_q + r1 + c * 16 + qp);
            qh[c][2] = *(const uint32_t*)(g_q + r0 + c * 16 + qp + 8);
            qh[c][3] = *(const uint32_t*)(g_q + r1 + c * 16 + qp + 8);
        }
    }

    float O[32];
#pragma unroll
    for (int i = 0; i < 32; i++) O[i] = 0.f;
    float lacc[4] = {0.f, 0.f, 0.f, 0.f};   // ones-mma accumulator (row sums)

    const int k_rhalf = (lane >> 4) << 3;
    const int k_csel  = (lane >> 3) & 1;
    const int k_i     = lane & 7;
    const int v_rhalf = ((lane >> 3) & 1) << 3;
    const int v_csel  = lane >> 4;

    auto fill = [&](int tt) {     // K/V only, double-buffered
        const int st = tt & 1;
        const uint32_t base = sb + st * KVST;
        const size_t krow = bS + kbase + tt * 64;
#pragma unroll
        for (int idx = tid; idx < 512; idx += 128) {
            const int r = idx >> 3, g = idx & 7;
            const uint32_t off = (uint32_t)(r * 128 + ((g ^ (r & 7)) * 16));
            const size_t so = (krow + r) * DK_ + g * 8;
            cp16(base + off,        g_k + so);
            cp16(base + 8192 + off, g_v + so);
        }
        cp_commit();
    };
    auto maskfill = [&](int tt) { // single buffer
        const int kk0 = kbase + tt * 64;
#pragma unroll
        for (int idx = tid; idx < 1024; idx += 128) {
            const int r = idx >> 4, c = idx & 15;
            cp16(sb + ASM_MASK + r * 272 + c * 16,
                 mask + (bS + q0 + r) * S_ + kk0 + c * 4);
        }
        cp_commit();
    };

    fill(0);
    maskfill(0);

    const int NT = S_ / NSPLIT / 64;   // 16 tiles
    for (int t = 0; t < NT; t++) {
        cp_wait<0>();
        __syncthreads();
        if (t + 1 < NT) fill(t + 1);

        const int st = t & 1;
        const uint32_t a_k = sb + st * KVST;
        const uint32_t a_v = a_k + 8192;
        const char* mptr = sm + ASM_MASK;

        // ---- scores + softmax + P fragments  (scores arrive pre-scaled: p = 2^cc)
        uint32_t ph[4][4];
#pragma unroll
        for (int nt2 = 0; nt2 < 4; nt2++) {
            float cA[4] = {0.f, 0.f, 0.f, 0.f};
            float cB[4] = {0.f, 0.f, 0.f, 0.f};
#pragma unroll
            for (int c = 0; c < 4; c++) {
                const int row = nt2 * 16 + k_rhalf + k_i;
                const uint32_t off = (uint32_t)(row * 128 + (((c * 2 + k_csel) ^ (row & 7)) * 16));
                uint32_t bh[4];
                ldsm4(bh, a_k + off);
                mma_f16(cA, qh[c], bh[0], bh[1]);
                mma_f16(cB, qh[c], bh[2], bh[3]);
            }
#pragma unroll
            for (int half = 0; half < 2; half++) {
                float* cc = half ? cB : cA;
                const int colw = nt2 * 16 + half * 8 + qp;
                const int2 mA = *(const int2*)(mptr + (wid * 16 + grp) * 272 + colw * 4);
                const int2 mB = *(const int2*)(mptr + (wid * 16 + grp + 8) * 272 + colw * 4);
                const float p0 = ex2f(mA.x ? cc[0] : -127.f);
                const float p1 = ex2f(mA.y ? cc[1] : -127.f);
                const float p2 = ex2f(mB.x ? cc[2] : -127.f);
                const float p3 = ex2f(mB.y ? cc[3] : -127.f);
                ph[nt2][half * 2 + 0] = cvt_f16x2(p0, p1);
                ph[nt2][half * 2 + 1] = cvt_f16x2(p2, p3);
            }
            // l += P @ ones  (row sums, fp32 accumulate; all 8 cols identical)
            mma_f16(lacc, ph[nt2], ONES_H2, ONES_H2);
        }

        // all warps done reading mask buffer -> refill it for t+1, hidden under PV
        __syncthreads();
        if (t + 1 < NT) maskfill(t + 1);

        // ---- O += P @ V  (single pass; row-major V via ldmatrix.trans)
#pragma unroll
        for (int dt2 = 0; dt2 < 4; dt2++) {
            float* oA = &O[dt2 * 8];
            float* oB = &O[dt2 * 8 + 4];
#pragma unroll
            for (int kc = 0; kc < 4; kc++) {
                const int row = kc * 16 + v_rhalf + k_i;
                const uint32_t off = (uint32_t)(row * 128 + (((dt2 * 2 + v_csel) ^ (row & 7)) * 16));
                uint32_t bh[4];
                ldsm4t(bh, a_v + off);
                mma_f16(oA, ph[kc], bh[0], bh[1]);
                mma_f16(oB, ph[kc], bh[2], bh[3]);
            }
        }
    }

    // ---- epilogue (lacc cols identical within quad; lacc[0]=row, lacc[2]=row+8)
    if ((lane & 3) == 0) {
        g_pl[sp][bS + qrow0 + grp]     = lacc[0];
        g_pl[sp][bS + qrow0 + grp + 8] = lacc[2];
    }
    float* dst0 = g_pacc[sp] + (bS + qrow0 + grp) * DK_;
    float* dst1 = dst0 + 8 * DK_;
#pragma unroll
    for (int dt = 0; dt < 8; dt++) {
        const int col = dt * 8 + qp;
        *(float2*)(dst0 + col) = make_float2(O[dt * 4 + 0], O[dt * 4 + 1]);
        *(float2*)(dst1 + col) = make_float2(O[dt * 4 + 2], O[dt * 4 + 3]);
    }
}

// ===========================================================================
// Merge the kv-splits: y = sum(acc) / sum(l)
// ===========================================================================
__global__ __launch_bounds__(256)
void merge_kernel(float* __restrict__ out)
{
    const int idx = blockIdx.x * 256 + threadIdx.x;
    const int r = idx >> 6;
    float l = 0.f, a = 0.f;
#pragma unroll
    for (int s = 0; s < NSPLIT; s++) {
        l += g_pl[s][r];
        a += g_pacc[s][idx];
    }
    out[idx] = a / l;
}

// ===========================================================================
extern "C" void kernel_launch(void* const* d_in, const int* in_sizes, int n_in,
                              void* d_out, int out_size)
{
    const float* Q    = (const float*)d_in[0];
    const float* K    = (const float*)d_in[1];
    const float* V    = (const float*)d_in[2];
    const int*   mask = (const int*)  d_in[3];
    const float* Wq   = (const float*)d_in[4];
    const float* bq   = (const float*)d_in[5];
    const float* Wk   = (const float*)d_in[6];
    const float* bk   = (const float*)d_in[7];
    const float* Wv   = (const float*)d_in[8];
    const float* bv   = (const float*)d_in[9];
    float* out = (float*)d_out;

    prep_w<<<dim3(DK_, 3), 256>>>(Wq, Wk, Wv);

    cudaFuncSetAttribute(proj_tc, cudaFuncAttributeMaxDynamicSharedMemorySize, PSM_TOTAL);
    proj_tc<<<dim3((B_ * S_) / 64, 3), 128, PSM_TOTAL>>>(Q, K, V, bq, bk, bv);

    cudaFuncSetAttribute(attn_mma_kernel,
                         cudaFuncAttributeMaxDynamicSharedMemorySize, ASM_TOTAL);
    attn_mma_kernel<<<dim3(S_ / 64, B_, NSPLIT), 128, ASM_TOTAL>>>(mask);

    merge_kernel<<<(B_ * S_ * DK_) / 256, 256>>>(out);
}

// round 17
// speedup vs baseline: 7.6308x; 1.0496x over previous
#include <cuda_runtime.h>
#include <cuda_bf16.h>
#include <cuda_fp16.h>
#include <cstdint>

#define B_   2
#define S_   4096
#define DM_  1024
#define DK_  64
#define NSPLIT 4

// ===========================================================================
// Scratch (__device__ globals per allocation rules)
// ===========================================================================
__device__ __half g_q [B_ * S_ * DK_];           // q * 0.125*log2e, fp16
__device__ __half g_k [B_ * S_ * DK_];           // k single fp16
__device__ __half g_v [B_ * S_ * DK_];           // v single fp16 (row-major)
__device__ __half g_w [3 * DK_ * DM_];           // W single fp16
__device__ float g_pacc[NSPLIT][B_ * S_ * DK_];  // per-split unnormalized O
__device__ float g_pl[NSPLIT][B_ * S_];          // per-split softmax denominators

__device__ __forceinline__ uint32_t smem_to_u32(const void* p) {
    uint32_t a;
    asm("{ .reg .u64 t; cvta.to.shared.u64 t, %1; cvt.u32.u64 %0, t; }" : "=r"(a) : "l"(p));
    return a;
}
__device__ __forceinline__ uint32_t pack_h2(__half a, __half b) {
    const __half2 v = __halves2half2(a, b);   // a -> low
    return *(const uint32_t*)&v;
}
__device__ __forceinline__ float ex2f(float x) {
    float y;
    asm("ex2.approx.f32 %0, %1;" : "=f"(y) : "f"(x));
    return y;
}
__device__ __forceinline__ uint32_t cvt_f16x2(float lo, float hi) {
    uint32_t d;
    asm("cvt.rn.f16x2.f32 %0, %1, %2;" : "=r"(d) : "f"(hi), "f"(lo));   // lo -> low half
    return d;
}
__device__ __forceinline__ void mma_f16(float c[4], const uint32_t a[4],
                                        uint32_t b0, uint32_t b1) {
    asm volatile("mma.sync.aligned.m16n8k16.row.col.f32.f16.f16.f32 "
        "{%0,%1,%2,%3}, {%4,%5,%6,%7}, {%8,%9}, {%0,%1,%2,%3};"
        : "+f"(c[0]), "+f"(c[1]), "+f"(c[2]), "+f"(c[3])
        : "r"(a[0]), "r"(a[1]), "r"(a[2]), "r"(a[3]), "r"(b0), "r"(b1));
}
__device__ __forceinline__ void ldsm4(uint32_t r[4], uint32_t addr) {
    asm volatile("ldmatrix.sync.aligned.m8n8.x4.shared.b16 {%0,%1,%2,%3}, [%4];"
        : "=r"(r[0]), "=r"(r[1]), "=r"(r[2]), "=r"(r[3]) : "r"(addr));
}
__device__ __forceinline__ void ldsm4t(uint32_t r[4], uint32_t addr) {
    asm volatile("ldmatrix.sync.aligned.m8n8.x4.trans.shared.b16 {%0,%1,%2,%3}, [%4];"
        : "=r"(r[0]), "=r"(r[1]), "=r"(r[2]), "=r"(r[3]) : "r"(addr));
}
__device__ __forceinline__ void cp16(uint32_t smem, const void* g) {
    asm volatile("cp.async.cg.shared.global [%0], [%1], 16;" :: "r"(smem), "l"(g));
}
__device__ __forceinline__ void cp_commit() {
    asm volatile("cp.async.commit_group;");
}
template <int N>
__device__ __forceinline__ void cp_wait() {
    asm volatile("cp.async.wait_group %0;" :: "n"(N));
}

// ===========================================================================
// prep_w: convert Wq/Wk/Wv fp32 -> single fp16 once.  grid (64, 3) x 256
// ===========================================================================
__global__ __launch_bounds__(256)
void prep_w(const float* __restrict__ Wq, const float* __restrict__ Wk,
            const float* __restrict__ Wv)
{
    const int which = blockIdx.y;
    const float* W = (which == 0) ? Wq : (which == 1) ? Wk : Wv;
    const int n = blockIdx.x;
    const int col = threadIdx.x * 4;
    const float4 v = *(const float4*)(W + n * DM_ + col);
    const size_t off = (size_t)which * DK_ * DM_ + n * DM_ + col;
    *(uint2*)(g_w + off) = make_uint2(
        pack_h2(__float2half_rn(v.x), __float2half_rn(v.y)),
        pack_h2(__float2half_rn(v.z), __float2half_rn(v.w)));
}

// ===========================================================================
// proj_tc: C[8192x64] = A @ W^T + bias, SINGLE-pass fp16 (A and W rounded).
// Epilogue: single-fp16 emit; q pre-scaled by 0.125*log2(e).
// CTA: 64 rows (4 warps x 16), K-chunks of 64.  grid (128, 3) x 128.
// smem: A 8K | W[2] 8K each = 24K
// ===========================================================================
#define PSM_A  0
#define PSM_W  8192           /* + stage*8192 */
#define PSM_TOTAL 24576
#define QSCALE 0.1803368801f  /* 0.125 * log2(e) */

__global__ __launch_bounds__(128)
void proj_tc(const float* __restrict__ Qin, const float* __restrict__ Kin,
             const float* __restrict__ Vin,
             const float* __restrict__ bq, const float* __restrict__ bk,
             const float* __restrict__ bv)
{
    extern __shared__ char ps[];
    const uint32_t sb = smem_to_u32(ps);

    const int which = blockIdx.y;
    const int tid  = threadIdx.x;
    const int wid  = tid >> 5;
    const int lane = tid & 31;

    const float* A    = (which == 0) ? Qin : (which == 1) ? Kin : Vin;
    const float* bias = (which == 0) ? bq  : (which == 1) ? bk  : bv;
    __half* D         = (which == 0) ? g_q : (which == 1) ? g_k : g_v;
    const float osc   = (which == 0) ? QSCALE : 1.0f;
    const __half* Wp  = g_w + (size_t)which * DK_ * DM_;

    const int m0 = blockIdx.x * 64;

    float c[8][4];
#pragma unroll
    for (int i = 0; i < 8; i++)
#pragma unroll
        for (int j = 0; j < 4; j++) c[i][j] = 0.f;

    const int arow  = wid * 16 + ((lane >> 3) & 1) * 8 + (lane & 7);
    const int acsel = lane >> 4;
    const int brow  = ((lane >> 4) << 3) + (lane & 7);
    const int bcsel = (lane >> 3) & 1;

    const int pr[4] = { (tid + 0)   >> 3, (tid + 128) >> 3,
                        (tid + 256) >> 3, (tid + 384) >> 3 };
    const int pg    = tid & 7;

    auto fillW = [&](int kc, int st) {
        const uint32_t wb = sb + PSM_W + st * 8192;
#pragma unroll
        for (int idx = tid; idx < 512; idx += 128) {
            const int n = idx >> 3, g = idx & 7;
            const uint32_t off = (uint32_t)(n * 128 + ((g ^ (n & 7)) * 16));
            cp16(wb + off, Wp + (size_t)n * DM_ + kc * 64 + g * 8);
        }
        cp_commit();
    };

    float4 aPre[8];
#pragma unroll
    for (int i = 0; i < 4; i++) {
        const float* src = A + (size_t)(m0 + pr[i]) * DM_ + pg * 8;
        aPre[2 * i]     = *(const float4*)src;
        aPre[2 * i + 1] = *(const float4*)(src + 4);
    }
    fillW(0, 0);

    for (int kc = 0; kc < 16; kc++) {
        cp_wait<0>();
        __syncthreads();
#pragma unroll
        for (int i = 0; i < 4; i++) {
            uint4 hv;
            hv.x = cvt_f16x2(aPre[2 * i].x,     aPre[2 * i].y);
            hv.y = cvt_f16x2(aPre[2 * i].z,     aPre[2 * i].w);
            hv.z = cvt_f16x2(aPre[2 * i + 1].x, aPre[2 * i + 1].y);
            hv.w = cvt_f16x2(aPre[2 * i + 1].z, aPre[2 * i + 1].w);
            const uint32_t off = (uint32_t)(pr[i] * 128 + ((pg ^ (pr[i] & 7)) * 16));
            *(uint4*)(ps + PSM_A + off) = hv;
        }
        if (kc < 15) {
#pragma unroll
            for (int i = 0; i < 4; i++) {
                const float* src = A + (size_t)(m0 + pr[i]) * DM_ + (kc + 1) * 64 + pg * 8;
                aPre[2 * i]     = *(const float4*)src;
                aPre[2 * i + 1] = *(const float4*)(src + 4);
            }
            fillW(kc + 1, (kc + 1) & 1);
        }
        __syncthreads();

        const uint32_t a_A = sb + PSM_A;
        const uint32_t a_W = sb + PSM_W + (kc & 1) * 8192;

        uint32_t ah[4][4];
#pragma unroll
        for (int k4 = 0; k4 < 4; k4++) {
            const int ch = k4 * 2 + acsel;
            const uint32_t off = (uint32_t)(arow * 128 + ((ch ^ (arow & 7)) * 16));
            ldsm4(ah[k4], a_A + off);
        }
#pragma unroll
        for (int nt = 0; nt < 4; nt++) {
            const int row = nt * 16 + brow;
#pragma unroll
            for (int k4 = 0; k4 < 4; k4++) {
                const int ch = k4 * 2 + bcsel;
                const uint32_t off = (uint32_t)(row * 128 + ((ch ^ (row & 7)) * 16));
                uint32_t wh[4];
                ldsm4(wh, a_W + off);
                mma_f16(c[nt * 2],     ah[k4], wh[0], wh[1]);
                mma_f16(c[nt * 2 + 1], ah[k4], wh[2], wh[3]);
            }
        }
    }

    // epilogue: bias (+ q pre-scale) + single fp16 emit
    const int grp = lane >> 2;
    const int qp  = (lane & 3) * 2;
    const size_t row0 = (size_t)(m0 + wid * 16 + grp);
    const size_t row1 = row0 + 8;
#pragma unroll
    for (int nt = 0; nt < 8; nt++) {
        const int col = nt * 8 + qp;
        const float b0 = bias[col], b1 = bias[col + 1];
        *(uint32_t*)(D + row0 * DK_ + col) =
            pack_h2(__float2half_rn((c[nt][0] + b0) * osc),
                    __float2half_rn((c[nt][1] + b1) * osc));
        *(uint32_t*)(D + row1 * DK_ + col) =
            pack_h2(__float2half_rn((c[nt][2] + b0) * osc),
                    __float2half_rn((c[nt][3] + b1) * osc));
    }
}

// ===========================================================================
// attention: 64-q CTA (4 warps x 16 rows), 64-key tiles, kv-split 4.
// Single-pass fp16; ex2 softmax; l via ones-mma.
// K/V double-buffered (2 x 16K); mask SINGLE 17K cp.async buffer refilled
// after softmax each tile.  smem 50176 -> 4 CTAs/SM -> single wave.
// ===========================================================================
#define KVST      16384        /* per K/V stage */
#define ASM_MASK  32768        /* single mask buffer, stride 272 */
#define ASM_TOTAL 50176
#define ONES_H2   0x3C003C00u

__global__ __launch_bounds__(128, 4)
void attn_mma_kernel(const int* __restrict__ mask)
{
    extern __shared__ char sm[];
    const uint32_t sb = smem_to_u32(sm);

    const int tid  = threadIdx.x;
    const int wid  = tid >> 5;
    const int lane = tid & 31;
    const int grp  = lane >> 2;
    const int qp   = (lane & 3) * 2;

    const int b     = blockIdx.y;
    const int sp    = blockIdx.z;
    const int q0    = blockIdx.x * 64;
    const int kbase = sp * (S_ / NSPLIT);
    const int qrow0 = q0 + wid * 16;
    const size_t bS = (size_t)b * S_;

    // Q fragments (single fp16, pre-scaled) from global, A-frag m16k16 layout
    uint32_t qh[4][4];
    {
        const size_t r0 = (bS + qrow0 + grp) * DK_;
        const size_t r1 = r0 + 8 * DK_;
#pragma unroll
        for (int c = 0; c < 4; c++) {
            qh[c][0] = *(const uint32_t*)(g_q + r0 + c * 16 + qp);
            qh[c][1] = *(const uint32_t*)(g_q + r1 + c * 16 + qp);
            qh[c][2] = *(const uint32_t*)(g_q + r0 + c * 16 + qp + 8);
            qh[c][3] = *(const uint32_t*)(g_q + r1 + c * 16 + qp + 8);
        }
    }

    float O[32];
#pragma unroll
    for (int i = 0; i < 32; i++) O[i] = 0.f;
    float lacc[4] = {0.f, 0.f, 0.f, 0.f};   // ones-mma accumulator (row sums)

    const int k_rhalf = (lane >> 4) << 3;
    const int k_csel  = (lane >> 3) & 1;
    const int k_i     = lane & 7;
    const int v_rhalf = ((lane >> 3) & 1) << 3;
    const int v_csel  = lane >> 4;

    auto fill = [&](int tt) {     // K/V only, double-buffered
        const int st = tt & 1;
        const uint32_t base = sb + st * KVST;
        const size_t krow = bS + kbase + tt * 64;
#pragma unroll
        for (int idx = tid; idx < 512; idx += 128) {
            const int r = idx >> 3, g = idx & 7;
            const uint32_t off = (uint32_t)(r * 128 + ((g ^ (r & 7)) * 16));
            const size_t so = (krow + r) * DK_ + g * 8;
            cp16(base + off,        g_k + so);
            cp16(base + 8192 + off, g_v + so);
        }
        cp_commit();
    };
    auto maskfill = [&](int tt) { // single buffer
        const int kk0 = kbase + tt * 64;
#pragma unroll
        for (int idx = tid; idx < 1024; idx += 128) {
            const int r = idx >> 4, c = idx & 15;
            cp16(sb + ASM_MASK + r * 272 + c * 16,
                 mask + (bS + q0 + r) * S_ + kk0 + c * 4);
        }
        cp_commit();
    };

    fill(0);
    maskfill(0);

    const int NT = S_ / NSPLIT / 64;   // 16 tiles
    for (int t = 0; t < NT; t++) {
        cp_wait<0>();
        __syncthreads();
        if (t + 1 < NT) fill(t + 1);

        const int st = t & 1;
        const uint32_t a_k = sb + st * KVST;
        const uint32_t a_v = a_k + 8192;
        const char* mptr = sm + ASM_MASK;

        // ---- scores + softmax + P fragments  (scores arrive pre-scaled: p = 2^cc)
        uint32_t ph[4][4];
#pragma unroll
        for (int nt2 = 0; nt2 < 4; nt2++) {
            float cA[4] = {0.f, 0.f, 0.f, 0.f};
            float cB[4] = {0.f, 0.f, 0.f, 0.f};
#pragma unroll
            for (int c = 0; c < 4; c++) {
                const int row = nt2 * 16 + k_rhalf + k_i;
                const uint32_t off = (uint32_t)(row * 128 + (((c * 2 + k_csel) ^ (row & 7)) * 16));
                uint32_t bh[4];
                ldsm4(bh, a_k + off);
                mma_f16(cA, qh[c], bh[0], bh[1]);
                mma_f16(cB, qh[c], bh[2], bh[3]);
            }
#pragma unroll
            for (int half = 0; half < 2; half++) {
                float* cc = half ? cB : cA;
                const int colw = nt2 * 16 + half * 8 + qp;
                const int2 mA = *(const int2*)(mptr + (wid * 16 + grp) * 272 + colw * 4);
                const int2 mB = *(const int2*)(mptr + (wid * 16 + grp + 8) * 272 + colw * 4);
                const float p0 = ex2f(mA.x ? cc[0] : -127.f);
                const float p1 = ex2f(mA.y ? cc[1] : -127.f);
                const float p2 = ex2f(mB.x ? cc[2] : -127.f);
                const float p3 = ex2f(mB.y ? cc[3] : -127.f);
                ph[nt2][half * 2 + 0] = cvt_f16x2(p0, p1);
                ph[nt2][half * 2 + 1] = cvt_f16x2(p2, p3);
            }
            // l += P @ ones  (row sums, fp32 accumulate; all 8 cols identical)
            mma_f16(lacc, ph[nt2], ONES_H2, ONES_H2);
        }

        // all warps done reading mask buffer -> refill it for t+1, hidden under PV
        __syncthreads();
        if (t + 1 < NT) maskfill(t + 1);

        // ---- O += P @ V  (single pass; row-major V via ldmatrix.trans)
#pragma unroll
        for (int dt2 = 0; dt2 < 4; dt2++) {
            float* oA = &O[dt2 * 8];
            float* oB = &O[dt2 * 8 + 4];
#pragma unroll
            for (int kc = 0; kc < 4; kc++) {
                const int row = kc * 16 + v_rhalf + k_i;
                const uint32_t off = (uint32_t)(row * 128 + (((dt2 * 2 + v_csel) ^ (row & 7)) * 16));
                uint32_t bh[4];
                ldsm4t(bh, a_v + off);
                mma_f16(oA, ph[kc], bh[0], bh[1]);
                mma_f16(oB, ph[kc], bh[2], bh[3]);
            }
        }
    }

    // ---- epilogue (lacc cols identical within quad; lacc[0]=row, lacc[2]=row+8)
    if ((lane & 3) == 0) {
        g_pl[sp][bS + qrow0 + grp]     = lacc[0];
        g_pl[sp][bS + qrow0 + grp + 8] = lacc[2];
    }
    float* dst0 = g_pacc[sp] + (bS + qrow0 + grp) * DK_;
    float* dst1 = dst0 + 8 * DK_;
#pragma unroll
    for (int dt = 0; dt < 8; dt++) {
        const int col = dt * 8 + qp;
        *(float2*)(dst0 + col) = make_float2(O[dt * 4 + 0], O[dt * 4 + 1]);
        *(float2*)(dst1 + col) = make_float2(O[dt * 4 + 2], O[dt * 4 + 3]);
    }
}

// ===========================================================================
// Merge the kv-splits: y = sum(acc) / sum(l)
// ===========================================================================
__global__ __launch_bounds__(256)
void merge_kernel(float* __restrict__ out)
{
    const int idx = blockIdx.x * 256 + threadIdx.x;
    const int r = idx >> 6;
    float l = 0.f, a = 0.f;
#pragma unroll
    for (int s = 0; s < NSPLIT; s++) {
        l += g_pl[s][r];
        a += g_pacc[s][idx];
    }
    out[idx] = a / l;
}

// ===========================================================================
extern "C" void kernel_launch(void* const* d_in, const int* in_sizes, int n_in,
                              void* d_out, int out_size)
{
    const float* Q    = (const float*)d_in[0];
    const float* K    = (const float*)d_in[1];
    const float* V    = (const float*)d_in[2];
    const int*   mask = (const int*)  d_in[3];
    const float* Wq   = (const float*)d_in[4];
    const float* bq   = (const float*)d_in[5];
    const float* Wk   = (const float*)d_in[6];
    const float* bk   = (const float*)d_in[7];
    const float* Wv   = (const float*)d_in[8];
    const float* bv   = (const float*)d_in[9];
    float* out = (float*)d_out;

    prep_w<<<dim3(DK_, 3), 256>>>(Wq, Wk, Wv);

    cudaFuncSetAttribute(proj_tc, cudaFuncAttributeMaxDynamicSharedMemorySize, PSM_TOTAL);
    proj_tc<<<dim3((B_ * S_) / 64, 3), 128, PSM_TOTAL>>>(Q, K, V, bq, bk, bv);

    cudaFuncSetAttribute(attn_mma_kernel,
                         cudaFuncAttributeMaxDynamicSharedMemorySize, ASM_TOTAL);
    attn_mma_kernel<<<dim3(S_ / 64, B_, NSPLIT), 128, ASM_TOTAL>>>(mask);

    merge_kernel<<<(B_ * S_ * DK_) / 256, 256>>>(out);
}